// round 2
// baseline (speedup 1.0000x reference)
#include <cuda_runtime.h>
#include <cuda_bf16.h>

// Problem constants
#define TT 4
#define EE 2048
#define PP 512
#define KK 5
#define DE 16
#define DH 128
#define P1 508   // P-K+1
#define P2 504   // P-2K+2

typedef unsigned long long u64;

// ---------------- scratch (device globals; no allocation allowed) ----------------
__device__ float d_elem[TT * EE * DE];     // [t][e][16]
__device__ float d_s0[TT * DE];            // sum over e of elem
__device__ float d_g1[TT * EE * DH];       // [t][e][128]
__device__ float d_s1[TT * DH];
__device__ int   d_gmax[TT * DH];          // float bits, non-negative

// ---------------- f32x2 helpers ----------------
__device__ __forceinline__ u64 pack2(float a, float b) {
    u64 r; asm("mov.b64 %0, {%1, %2};" : "=l"(r) : "f"(a), "f"(b)); return r;
}
__device__ __forceinline__ void unpack2(u64 v, float& a, float& b) {
    asm("mov.b64 {%0, %1}, %2;" : "=f"(a), "=f"(b) : "l"(v));
}
__device__ __forceinline__ void fma2(u64& d, u64 a, u64 b) {
    asm("fma.rn.f32x2 %0, %1, %2, %0;" : "+l"(d) : "l"(a), "l"(b));
}

// ---------------- K0: init gmax ----------------
__global__ void k_init() {
    int i = threadIdx.x;
    if (i < TT * DH) d_gmax[i] = 0;
}

// ---------------- K1: conv1 + conv2 + point-sum -> elem_latent ----------------
// grid (E, T), block 128
__global__ __launch_bounds__(128) void k_conv(
    const float* __restrict__ points,
    const float* __restrict__ w1, const float* __restrict__ b1,
    const float* __restrict__ w2, const float* __restrict__ b2)
{
    __shared__ float pts[2][PP];
    __shared__ float h1[DE][PP];           // valid columns 0..507
    __shared__ __align__(16) float w2sp[80][16];  // [ci*5+k][co]
    __shared__ float w1s[160];
    __shared__ float b1s[16], b2s[16];
    __shared__ float redw[4][16];

    const int tid = threadIdx.x;
    const int t = blockIdx.y, e = blockIdx.x;

    // ---- stage inputs ----
    const float2* pin2 = reinterpret_cast<const float2*>(points + (size_t)(t * EE + e) * PP * 2);
    #pragma unroll
    for (int j = 0; j < 4; j++) {
        int p = tid + j * 128;
        float2 v = pin2[p];
        pts[0][p] = v.x; pts[1][p] = v.y;
    }
    for (int i = tid; i < 160; i += 128) w1s[i] = w1[t * 160 + i];
    for (int i = tid; i < 1280; i += 128) w2sp[i % 80][i / 80] = w2[t * 1280 + i];
    if (tid < 16) { b1s[tid] = b1[t * 16 + tid]; b2s[tid] = b2[t * 16 + tid]; }
    __syncthreads();

    // ---- conv1: h1[co][p] = relu(b1 + sum_{ci,k} w1[co][ci][k] * pts[ci][p+k]) ----
    float xr[4][5], yr[4][5];
    #pragma unroll
    for (int j = 0; j < 4; j++) {
        int p = tid + j * 128;
        int pc = (p < P1) ? p : (P1 - 1);   // clamp; masked at store
        #pragma unroll
        for (int k = 0; k < 5; k++) { xr[j][k] = pts[0][pc + k]; yr[j][k] = pts[1][pc + k]; }
    }
    #pragma unroll 1
    for (int co = 0; co < 16; co++) {
        float wc[10];
        #pragma unroll
        for (int q = 0; q < 10; q++) wc[q] = w1s[co * 10 + q];
        float bb = b1s[co];
        #pragma unroll
        for (int j = 0; j < 4; j++) {
            int p = tid + j * 128;
            float a = bb;
            #pragma unroll
            for (int k = 0; k < 5; k++) a = fmaf(wc[k], xr[j][k], a);
            #pragma unroll
            for (int k = 0; k < 5; k++) a = fmaf(wc[5 + k], yr[j][k], a);
            if (p < P1) h1[co][p] = fmaxf(a, 0.0f);
        }
    }
    __syncthreads();

    // ---- conv2 (packed f32x2, co-pairs) + per-position relu + point sum ----
    const int p0 = tid, pa = tid + 128, pb = tid + 256;
    const int p3 = (tid + 384 < P2) ? (tid + 384) : (P2 - 1);  // clamp; masked later

    u64 acc[4][8];
    #pragma unroll
    for (int cp = 0; cp < 8; cp++) {
        u64 bi = pack2(b2s[2 * cp], b2s[2 * cp + 1]);
        acc[0][cp] = bi; acc[1][cp] = bi; acc[2][cp] = bi; acc[3][cp] = bi;
    }

    #pragma unroll 1
    for (int ci = 0; ci < 16; ci++) {
        const float* hrow = h1[ci];
        const u64* wrow = reinterpret_cast<const u64*>(&w2sp[ci * 5][0]);
        #pragma unroll
        for (int k = 0; k < 5; k++) {
            float h0 = hrow[p0 + k], h1v = hrow[pa + k], h2 = hrow[pb + k], h3 = hrow[p3 + k];
            u64 hp0 = pack2(h0, h0);
            u64 hp1 = pack2(h1v, h1v);
            u64 hp2 = pack2(h2, h2);
            u64 hp3 = pack2(h3, h3);
            #pragma unroll
            for (int cp = 0; cp < 8; cp++) {
                u64 w = wrow[k * 8 + cp];
                fma2(acc[0][cp], w, hp0);
                fma2(acc[1][cp], w, hp1);
                fma2(acc[2][cp], w, hp2);
                fma2(acc[3][cp], w, hp3);
            }
        }
    }

    // relu each position, sum over this thread's positions (mask j=3 tail)
    float s16[16];
    const bool m3 = (tid + 384 < P2);
    #pragma unroll
    for (int cp = 0; cp < 8; cp++) {
        float a0, c0, a1, c1, a2, c2, a3, c3;
        unpack2(acc[0][cp], a0, c0);
        unpack2(acc[1][cp], a1, c1);
        unpack2(acc[2][cp], a2, c2);
        unpack2(acc[3][cp], a3, c3);
        float se = fmaxf(a0, 0.f) + fmaxf(a1, 0.f) + fmaxf(a2, 0.f);
        float so = fmaxf(c0, 0.f) + fmaxf(c1, 0.f) + fmaxf(c2, 0.f);
        if (m3) { se += fmaxf(a3, 0.f); so += fmaxf(c3, 0.f); }
        s16[2 * cp] = se; s16[2 * cp + 1] = so;
    }

    // reduce over 128 threads
    #pragma unroll
    for (int co = 0; co < 16; co++) {
        float v = s16[co];
        #pragma unroll
        for (int o = 16; o > 0; o >>= 1) v += __shfl_xor_sync(0xffffffffu, v, o);
        s16[co] = v;
    }
    const int lane = tid & 31, warp = tid >> 5;
    if (lane == 0) {
        #pragma unroll
        for (int co = 0; co < 16; co++) redw[warp][co] = s16[co];
    }
    __syncthreads();
    if (tid < 16)
        d_elem[(size_t)(t * EE + e) * 16 + tid] =
            redw[0][tid] + redw[1][tid] + redw[2][tid] + redw[3][tid];
}

// ---------------- K2: s0[t][d] = sum_e elem ----------------
__global__ void k_sum0() {
    int t = blockIdx.x, tid = threadIdx.x;
    int d = tid & 15, grp = tid >> 4;   // 16 groups
    float acc = 0.f;
    for (int e = grp; e < EE; e += 16) acc += d_elem[(t * EE + e) * 16 + d];
    __shared__ float r[256];
    r[tid] = acc; __syncthreads();
    for (int o = 128; o >= 16; o >>= 1) {
        if (tid < o) r[tid] += r[tid + o];
        __syncthreads();
    }
    if (tid < 16) d_s0[t * 16 + tid] = r[tid];
}

// ---------------- K3: layer1  g1 = relu(elem@(A1-B1) + s0@B1) ----------------
// grid (64, T), block 128
__global__ __launch_bounds__(128) void k_layer1(
    const float* __restrict__ A1, const float* __restrict__ B1)
{
    __shared__ float C1s[16][128];
    __shared__ float el[32][16];
    const int tid = threadIdx.x, t = blockIdx.y, e0 = blockIdx.x * 32;

    for (int i = tid; i < 2048; i += 128)
        C1s[i >> 7][i & 127] = A1[t * 2048 + i] - B1[t * 2048 + i];
    float sb = 0.f;
    #pragma unroll
    for (int d = 0; d < 16; d++)
        sb = fmaf(d_s0[t * 16 + d], B1[t * 2048 + d * 128 + tid], sb);
    for (int i = tid; i < 512; i += 128)
        el[i >> 4][i & 15] = d_elem[(t * EE + e0) * 16 + i];
    __syncthreads();

    #pragma unroll 1
    for (int ei = 0; ei < 32; ei++) {
        float a = sb;
        #pragma unroll
        for (int d = 0; d < 16; d++) a = fmaf(el[ei][d], C1s[d][tid], a);
        d_g1[(size_t)(t * EE + e0 + ei) * 128 + tid] = fmaxf(a, 0.f);
    }
}

// ---------------- K4: s1[t][h] = sum_e g1 ----------------
__global__ void k_sum1() {
    int t = blockIdx.x, tid = threadIdx.x;
    int h = tid & 127, grp = tid >> 7;
    float acc = 0.f;
    for (int e = grp; e < EE; e += 2) acc += d_g1[(t * EE + e) * 128 + h];
    __shared__ float r[256];
    r[tid] = acc; __syncthreads();
    if (tid < 128) d_s1[t * 128 + tid] = r[tid] + r[tid + 128];
}

// ---------------- K5: layer2 + max over e (atomicMax on float bits) ----------------
// grid (64, T), block 128
__global__ __launch_bounds__(128) void k_layer2(
    const float* __restrict__ A2, const float* __restrict__ B2)
{
    __shared__ float C2s[64][128];   // 32 KB
    __shared__ float g1s[32][64];    // 8 KB
    const int tid = threadIdx.x, t = blockIdx.y, e0 = blockIdx.x * 32;
    const int tb = t * 16384;

    float sb = 0.f;
    for (int d = 0; d < 128; d++)
        sb = fmaf(d_s1[t * 128 + d], B2[tb + d * 128 + tid], sb);

    float acc[32];
    #pragma unroll
    for (int ei = 0; ei < 32; ei++) acc[ei] = sb;

    for (int half = 0; half < 2; half++) {
        int d0 = half * 64;
        __syncthreads();
        for (int i = tid; i < 8192; i += 128) {
            int d = i >> 7, h = i & 127;
            C2s[d][h] = A2[tb + (d0 + d) * 128 + h] - B2[tb + (d0 + d) * 128 + h];
        }
        for (int i = tid; i < 2048; i += 128) {
            int ei = i >> 6, dd = i & 63;
            g1s[ei][dd] = d_g1[(size_t)(t * EE + e0 + ei) * 128 + d0 + dd];
        }
        __syncthreads();
        #pragma unroll 1
        for (int dd = 0; dd < 64; dd++) {
            float c = C2s[dd][tid];
            #pragma unroll
            for (int ei = 0; ei < 32; ei++) acc[ei] = fmaf(g1s[ei][dd], c, acc[ei]);
        }
    }

    float m = 0.f;  // relu floor == max identity here
    #pragma unroll
    for (int ei = 0; ei < 32; ei++) m = fmaxf(m, acc[ei]);
    atomicMax(&d_gmax[t * 128 + tid], __float_as_int(fmaxf(m, 0.f)));
}

// ---------------- K6: g@Aout per type, concat, @W_map + b_map ----------------
__global__ void k_final(const float* __restrict__ Aout,
                        const float* __restrict__ Wm,
                        const float* __restrict__ bm,
                        float* __restrict__ out)
{
    __shared__ float gv[512], gf[512];
    const int tid = threadIdx.x;
    for (int i = tid; i < 512; i += 256) gv[i] = __int_as_float(d_gmax[i]);
    __syncthreads();
    for (int idx = tid; idx < 512; idx += 256) {
        int t = idx >> 7, o = idx & 127;
        float a = 0.f;
        for (int h = 0; h < 128; h++)
            a = fmaf(gv[t * 128 + h], Aout[t * 16384 + h * 128 + o], a);
        gf[idx] = a;
    }
    __syncthreads();
    if (tid < 256) {
        float a = bm[tid];
        for (int i = 0; i < 512; i++) a = fmaf(gf[i], Wm[i * 256 + tid], a);
        out[tid] = a;
    }
}

// ---------------- launch ----------------
extern "C" void kernel_launch(void* const* d_in, const int* in_sizes, int n_in,
                              void* d_out, int out_size)
{
    const float* points = (const float*)d_in[0];
    const float* w1     = (const float*)d_in[1];
    const float* b1     = (const float*)d_in[2];
    const float* w2     = (const float*)d_in[3];
    const float* b2     = (const float*)d_in[4];
    const float* A1     = (const float*)d_in[5];
    const float* B1     = (const float*)d_in[6];
    const float* A2     = (const float*)d_in[7];
    const float* B2     = (const float*)d_in[8];
    const float* Aout   = (const float*)d_in[9];
    const float* Wm     = (const float*)d_in[10];
    const float* bm     = (const float*)d_in[11];
    float* out = (float*)d_out;

    k_init<<<1, 512>>>();
    k_conv<<<dim3(EE, TT), 128>>>(points, w1, b1, w2, b2);
    k_sum0<<<TT, 256>>>();
    k_layer1<<<dim3(EE / 32, TT), 128>>>(A1, B1);
    k_sum1<<<TT, 256>>>();
    k_layer2<<<dim3(EE / 32, TT), 128>>>(A2, B2);
    k_final<<<1, 256>>>(Aout, Wm, bm, out);
}

// round 3
// speedup vs baseline: 1.1452x; 1.1452x over previous
#include <cuda_runtime.h>
#include <cuda_bf16.h>

#define TT 4
#define EE 2048
#define PP 512
#define DE 16
#define DH 128
#define P1 508   // P-K+1
#define P2 504   // P-2K+2

typedef unsigned long long u64;

// ---------------- scratch (device globals) ----------------
__device__ float d_elem[TT * EE * DE];       // [t][e][16]
__device__ float d_s0p[TT * 16 * 16];        // s0 partials [t][b][16]
__device__ float d_s1p[TT * 32 * DH];        // s1 partials [t][b][128]
__device__ int   d_gmax[TT * DH];            // float bits, >= 0
__device__ float d_gf[TT * DH];              // per-type latents after Aout
__device__ float d_fpart[8 * 256];           // final matmul partials

// ---------------- f32x2 helpers ----------------
__device__ __forceinline__ u64 pack2(float a, float b) {
    u64 r; asm("mov.b64 %0, {%1, %2};" : "=l"(r) : "f"(a), "f"(b)); return r;
}
__device__ __forceinline__ void unpack2(u64 v, float& a, float& b) {
    asm("mov.b64 {%0, %1}, %2;" : "=f"(a), "=f"(b) : "l"(v));
}
__device__ __forceinline__ void fma2(u64& d, u64 a, u64 b) {
    asm("fma.rn.f32x2 %0, %1, %2, %0;" : "+l"(d) : "l"(a), "l"(b));
}

// ---------------- K0: init gmax ----------------
__global__ void k_init() {
    int i = threadIdx.x;
    if (i < TT * DH) d_gmax[i] = 0;
}

// ---------------- K1: conv1 + conv2 + point-sum -> elem_latent ----------------
// grid (E, T), block 128
__global__ __launch_bounds__(128) void k_conv(
    const float* __restrict__ points,
    const float* __restrict__ w1, const float* __restrict__ b1,
    const float* __restrict__ w2, const float* __restrict__ b2)
{
    __shared__ float pts[2][PP];
    __shared__ float h1[DE][PP];                  // valid cols 0..507
    __shared__ __align__(16) float w2sp[80][16];  // [ci*5+k][co]
    __shared__ float w1s[160];
    __shared__ float b1s[16], b2s[16];
    __shared__ float redw[4][16];

    const int tid = threadIdx.x;
    const int t = blockIdx.y, e = blockIdx.x;

    // ---- stage inputs ----
    const float2* pin2 = reinterpret_cast<const float2*>(points + (size_t)(t * EE + e) * PP * 2);
    #pragma unroll
    for (int j = 0; j < 4; j++) {
        int p = tid + j * 128;
        float2 v = pin2[p];
        pts[0][p] = v.x; pts[1][p] = v.y;
    }
    for (int i = tid; i < 160; i += 128) w1s[i] = w1[t * 160 + i];
    for (int i = tid; i < 1280; i += 128) w2sp[i % 80][i / 80] = w2[t * 1280 + i];
    if (tid < 16) { b1s[tid] = b1[t * 16 + tid]; b2s[tid] = b2[t * 16 + tid]; }
    __syncthreads();

    // ---- conv1 (packed f32x2, position pairs) ----
    u64 xp[2][5], yp[2][5];
    #pragma unroll
    for (int pr = 0; pr < 2; pr++) {
        int pA = tid + (2 * pr) * 128;
        int pB = tid + (2 * pr + 1) * 128;
        int pAc = (pA < P1) ? pA : (P1 - 1);
        int pBc = (pB < P1) ? pB : (P1 - 1);
        #pragma unroll
        for (int k = 0; k < 5; k++) {
            xp[pr][k] = pack2(pts[0][pAc + k], pts[0][pBc + k]);
            yp[pr][k] = pack2(pts[1][pAc + k], pts[1][pBc + k]);
        }
    }
    const bool m1 = (tid + 384 < P1);
    #pragma unroll 1
    for (int co = 0; co < 16; co++) {
        float wc[10];
        #pragma unroll
        for (int q = 0; q < 10; q++) wc[q] = w1s[co * 10 + q];
        float bb = b1s[co];
        u64 a0 = pack2(bb, bb), a1 = a0;
        #pragma unroll
        for (int k = 0; k < 5; k++) {
            u64 w = pack2(wc[k], wc[k]);
            fma2(a0, w, xp[0][k]);
            fma2(a1, w, xp[1][k]);
        }
        #pragma unroll
        for (int k = 0; k < 5; k++) {
            u64 w = pack2(wc[5 + k], wc[5 + k]);
            fma2(a0, w, yp[0][k]);
            fma2(a1, w, yp[1][k]);
        }
        float v0, v1, v2, v3;
        unpack2(a0, v0, v1);
        unpack2(a1, v2, v3);
        h1[co][tid]       = fmaxf(v0, 0.f);
        h1[co][tid + 128] = fmaxf(v1, 0.f);
        h1[co][tid + 256] = fmaxf(v2, 0.f);
        if (m1) h1[co][tid + 384] = fmaxf(v3, 0.f);
    }
    __syncthreads();

    // ---- conv2 (packed f32x2, co-pairs) + per-position relu + point sum ----
    const int p0 = tid, pa = tid + 128, pb = tid + 256;
    const int p3 = (tid + 384 < P2) ? (tid + 384) : (P2 - 1);

    u64 acc[4][8];
    #pragma unroll
    for (int cp = 0; cp < 8; cp++) {
        u64 bi = pack2(b2s[2 * cp], b2s[2 * cp + 1]);
        acc[0][cp] = bi; acc[1][cp] = bi; acc[2][cp] = bi; acc[3][cp] = bi;
    }

    #pragma unroll 1
    for (int ci = 0; ci < 16; ci++) {
        const float* hrow = h1[ci];
        const u64* wrow = reinterpret_cast<const u64*>(&w2sp[ci * 5][0]);
        #pragma unroll
        for (int k = 0; k < 5; k++) {
            float h0 = hrow[p0 + k], h1v = hrow[pa + k], h2 = hrow[pb + k], h3 = hrow[p3 + k];
            u64 hp0 = pack2(h0, h0);
            u64 hp1 = pack2(h1v, h1v);
            u64 hp2 = pack2(h2, h2);
            u64 hp3 = pack2(h3, h3);
            #pragma unroll
            for (int cp = 0; cp < 8; cp++) {
                u64 w = wrow[k * 8 + cp];
                fma2(acc[0][cp], w, hp0);
                fma2(acc[1][cp], w, hp1);
                fma2(acc[2][cp], w, hp2);
                fma2(acc[3][cp], w, hp3);
            }
        }
    }

    float s16[16];
    const bool m3 = (tid + 384 < P2);
    #pragma unroll
    for (int cp = 0; cp < 8; cp++) {
        float a0, c0, a1, c1, a2, c2, a3, c3;
        unpack2(acc[0][cp], a0, c0);
        unpack2(acc[1][cp], a1, c1);
        unpack2(acc[2][cp], a2, c2);
        unpack2(acc[3][cp], a3, c3);
        float se = fmaxf(a0, 0.f) + fmaxf(a1, 0.f) + fmaxf(a2, 0.f);
        float so = fmaxf(c0, 0.f) + fmaxf(c1, 0.f) + fmaxf(c2, 0.f);
        if (m3) { se += fmaxf(a3, 0.f); so += fmaxf(c3, 0.f); }
        s16[2 * cp] = se; s16[2 * cp + 1] = so;
    }

    #pragma unroll
    for (int co = 0; co < 16; co++) {
        float v = s16[co];
        #pragma unroll
        for (int o = 16; o > 0; o >>= 1) v += __shfl_xor_sync(0xffffffffu, v, o);
        s16[co] = v;
    }
    const int lane = tid & 31, warp = tid >> 5;
    if (lane == 0) {
        #pragma unroll
        for (int co = 0; co < 16; co++) redw[warp][co] = s16[co];
    }
    __syncthreads();
    if (tid < 16)
        d_elem[(size_t)(t * EE + e) * 16 + tid] =
            redw[0][tid] + redw[1][tid] + redw[2][tid] + redw[3][tid];
}

// ---------------- K2: s0 partials  grid (16, T), block 128 ----------------
__global__ void k_s0p() {
    const int t = blockIdx.y, b = blockIdx.x, tid = threadIdx.x;
    const int d = tid & 15, grp = tid >> 4;   // 8 groups of 16 e's
    float acc = 0.f;
    #pragma unroll 4
    for (int i = 0; i < 16; i++) {
        int e = b * 128 + grp + 8 * i;
        acc += d_elem[(size_t)(t * EE + e) * 16 + d];
    }
    __shared__ float r[128];
    r[tid] = acc; __syncthreads();
    if (tid < 64) r[tid] += r[tid + 64];
    __syncthreads();
    if (tid < 32) r[tid] += r[tid + 32];
    __syncthreads();
    if (tid < 16) d_s0p[(t * 16 + b) * 16 + tid] = r[tid] + r[tid + 16];
}

// ---------------- K3: s1 partials (computes g1 on the fly) ----------------
// grid (32, T), block 128; each block handles 64 e's
__global__ __launch_bounds__(128) void k_s1p(
    const float* __restrict__ A1, const float* __restrict__ B1)
{
    __shared__ float C1s[16][128];
    __shared__ float s0s[16];
    __shared__ float elems[64][16];
    const int tid = threadIdx.x, t = blockIdx.y, e0 = blockIdx.x * 64;

    for (int i = tid; i < 2048; i += 128)
        C1s[i >> 7][i & 127] = A1[t * 2048 + i] - B1[t * 2048 + i];
    if (tid < 16) {
        float s = 0.f;
        #pragma unroll
        for (int b = 0; b < 16; b++) s += d_s0p[(t * 16 + b) * 16 + tid];
        s0s[tid] = s;
    }
    for (int i = tid; i < 1024; i += 128)
        elems[i >> 4][i & 15] = d_elem[(size_t)(t * EE + e0) * 16 + i];
    __syncthreads();

    float c1r[16];
    #pragma unroll
    for (int d = 0; d < 16; d++) c1r[d] = C1s[d][tid];
    float sbl1 = 0.f;
    #pragma unroll
    for (int d = 0; d < 16; d++)
        sbl1 = fmaf(s0s[d], B1[t * 2048 + d * 128 + tid], sbl1);

    float acc = 0.f;
    #pragma unroll 4
    for (int ei = 0; ei < 64; ei++) {
        float v = sbl1;
        #pragma unroll
        for (int d = 0; d < 16; d++) v = fmaf(elems[ei][d], c1r[d], v);
        acc += fmaxf(v, 0.f);
    }
    d_s1p[(t * 32 + blockIdx.x) * 128 + tid] = acc;
}

// ---------------- K4: layer2 (g1 recomputed) + max over e ----------------
// grid (64, T), block 128; each block handles 32 e's
__global__ __launch_bounds__(128) void k_layer2(
    const float* __restrict__ A1, const float* __restrict__ B1,
    const float* __restrict__ A2, const float* __restrict__ B2)
{
    __shared__ float s0s[16];
    __shared__ float s1s[128];
    __shared__ __align__(8) float g1T[128][34];   // [feature d][ei], pad 34
    union Shm {
        struct { float C1s[16][128]; float elems[32][16]; } ph1;
        float C2q[32][128];
    };
    __shared__ Shm u;

    const int tid = threadIdx.x, t = blockIdx.y, e0 = blockIdx.x * 32;
    const int tb = t * 16384;

    // --- stage phase-1 data ---
    if (tid < 16) {
        float s = 0.f;
        #pragma unroll
        for (int b = 0; b < 16; b++) s += d_s0p[(t * 16 + b) * 16 + tid];
        s0s[tid] = s;
    }
    {
        float s = 0.f;
        #pragma unroll 4
        for (int b = 0; b < 32; b++) s += d_s1p[(t * 32 + b) * 128 + tid];
        s1s[tid] = s;
    }
    for (int i = tid; i < 2048; i += 128)
        u.ph1.C1s[i >> 7][i & 127] = A1[t * 2048 + i] - B1[t * 2048 + i];
    for (int i = tid; i < 512; i += 128)
        u.ph1.elems[i >> 4][i & 15] = d_elem[(size_t)(t * EE + e0) * 16 + i];
    __syncthreads();

    // --- recompute g1 for this block's 32 e's, store transposed ---
    {
        float c1r[16];
        #pragma unroll
        for (int d = 0; d < 16; d++) c1r[d] = u.ph1.C1s[d][tid];
        float sbl1 = 0.f;
        #pragma unroll
        for (int d = 0; d < 16; d++)
            sbl1 = fmaf(s0s[d], B1[t * 2048 + d * 128 + tid], sbl1);
        #pragma unroll 2
        for (int ei = 0; ei < 32; ei++) {
            float v = sbl1;
            #pragma unroll
            for (int d = 0; d < 16; d++) v = fmaf(u.ph1.elems[ei][d], c1r[d], v);
            g1T[tid][ei] = fmaxf(v, 0.f);
        }
    }

    // --- sb = s1 @ B2 column(tid) ---
    float sb = 0.f;
    #pragma unroll 4
    for (int d = 0; d < 128; d++)
        sb = fmaf(s1s[d], B2[tb + d * 128 + tid], sb);

    // --- main GEMM: acc[ei] = sb + sum_d g1[ei][d] * C2[d][tid], f32x2 ei-pairs ---
    u64 acc[16];
    #pragma unroll
    for (int pr = 0; pr < 16; pr++) acc[pr] = pack2(sb, sb);

    for (int q = 0; q < 4; q++) {
        const int d0 = q * 32;
        __syncthreads();
        for (int i = tid; i < 4096; i += 128) {
            int d = i >> 7, h = i & 127;
            u.C2q[d][h] = A2[tb + (d0 + d) * 128 + h] - B2[tb + (d0 + d) * 128 + h];
        }
        __syncthreads();
        #pragma unroll 4
        for (int dd = 0; dd < 32; dd++) {
            float c = u.C2q[dd][tid];
            u64 cp = pack2(c, c);
            const u64* grow = reinterpret_cast<const u64*>(&g1T[d0 + dd][0]);
            #pragma unroll
            for (int pr = 0; pr < 16; pr++) fma2(acc[pr], grow[pr], cp);
        }
    }

    float m = 0.f;  // relu floor == max identity
    #pragma unroll
    for (int pr = 0; pr < 16; pr++) {
        float a, b;
        unpack2(acc[pr], a, b);
        m = fmaxf(m, fmaxf(a, b));
    }
    atomicMax(&d_gmax[t * 128 + tid], __float_as_int(m));
}

// ---------------- K5: gf[t][o] = gmax[t] @ Aout[t] ----------------
__global__ void k_gf(const float* __restrict__ Aout) {
    __shared__ float gs[128];
    const int t = blockIdx.x, tid = threadIdx.x;
    gs[tid] = __int_as_float(d_gmax[t * 128 + tid]);
    __syncthreads();
    float a = 0.f;
    #pragma unroll 4
    for (int h = 0; h < 128; h++)
        a = fmaf(gs[h], Aout[t * 16384 + h * 128 + tid], a);
    d_gf[t * 128 + tid] = a;
}

// ---------------- K6a: final matmul partials  grid 8, block 256 ----------------
__global__ void k_fin1(const float* __restrict__ Wm) {
    __shared__ float gfs[512];
    const int b = blockIdx.x, tid = threadIdx.x;
    for (int i = tid; i < 512; i += 256) gfs[i] = d_gf[i];
    __syncthreads();
    float a = 0.f;
    const int i0 = b * 64;
    #pragma unroll 8
    for (int i = 0; i < 64; i++)
        a = fmaf(gfs[i0 + i], Wm[(i0 + i) * 256 + tid], a);
    d_fpart[b * 256 + tid] = a;
}

// ---------------- K6b: combine ----------------
__global__ void k_fin2(const float* __restrict__ bm, float* __restrict__ out) {
    const int tid = threadIdx.x;
    float a = bm[tid];
    #pragma unroll
    for (int b = 0; b < 8; b++) a += d_fpart[b * 256 + tid];
    out[tid] = a;
}

// ---------------- launch ----------------
extern "C" void kernel_launch(void* const* d_in, const int* in_sizes, int n_in,
                              void* d_out, int out_size)
{
    const float* points = (const float*)d_in[0];
    const float* w1     = (const float*)d_in[1];
    const float* b1     = (const float*)d_in[2];
    const float* w2     = (const float*)d_in[3];
    const float* b2     = (const float*)d_in[4];
    const float* A1     = (const float*)d_in[5];
    const float* B1     = (const float*)d_in[6];
    const float* A2     = (const float*)d_in[7];
    const float* B2     = (const float*)d_in[8];
    const float* Aout   = (const float*)d_in[9];
    const float* Wm     = (const float*)d_in[10];
    const float* bm     = (const float*)d_in[11];
    float* out = (float*)d_out;

    k_init<<<1, 512>>>();
    k_conv<<<dim3(EE, TT), 128>>>(points, w1, b1, w2, b2);
    k_s0p<<<dim3(16, TT), 128>>>();
    k_s1p<<<dim3(32, TT), 128>>>(A1, B1);
    k_layer2<<<dim3(64, TT), 128>>>(A1, B1, A2, B2);
    k_gf<<<TT, 128>>>(Aout);
    k_fin1<<<8, 256>>>(Wm);
    k_fin2<<<1, 256>>>(bm, out);
}

// round 5
// speedup vs baseline: 1.1502x; 1.0044x over previous
#include <cuda_runtime.h>
#include <cuda_bf16.h>

#define TT 4
#define EE 2048
#define PP 512
#define DE 16
#define DH 128
#define P1 508   // P-K+1
#define P2 504   // P-2K+2

typedef unsigned long long u64;

// ---------------- scratch (device globals) ----------------
__device__ float d_elem[TT * EE * DE];        // [t][e][16]
__device__ float d_s0p[TT * 32 * 16];         // s0 partials [t][chunk][16]
__device__ float d_s1p[TT * 64 * DH];         // s1 partials [t][slot][128]
__device__ int   d_gmax[TT * DH];             // float bits, >= 0
__device__ float d_gf[TT * DH];
__device__ float d_fpart[8 * 256];
__device__ unsigned d_bar_count = 0;
__device__ unsigned d_bar_gen = 0;

// ---------------- f32x2 helpers ----------------
__device__ __forceinline__ u64 pack2(float a, float b) {
    u64 r; asm("mov.b64 %0, {%1, %2};" : "=l"(r) : "f"(a), "f"(b)); return r;
}
__device__ __forceinline__ void unpack2(u64 v, float& a, float& b) {
    asm("mov.b64 {%0, %1}, %2;" : "=f"(a), "=f"(b) : "l"(v));
}
__device__ __forceinline__ void fma2(u64& d, u64 a, u64 b) {
    asm("fma.rn.f32x2 %0, %1, %2, %0;" : "+l"(d) : "l"(a), "l"(b));
}

// ---------------- grid barrier (all blocks co-resident: grid<=128) ----------------
__device__ __forceinline__ void gbar(unsigned expected) {
    __syncthreads();
    if (threadIdx.x == 0) {
        __threadfence();
        unsigned g = atomicAdd(&d_bar_gen, 0u);
        if (atomicAdd(&d_bar_count, 1u) == expected - 1u) {
            d_bar_count = 0u;
            __threadfence();
            atomicAdd(&d_bar_gen, 1u);
        } else {
            while (atomicAdd(&d_bar_gen, 0u) == g) { __nanosleep(20); }
        }
        __threadfence();
    }
    __syncthreads();
}

// ---------------- K1: conv1 + conv2 + point-sum -> elem_latent ----------------
// grid (E, T), block 128
__global__ __launch_bounds__(128) void k_conv(
    const float* __restrict__ points,
    const float* __restrict__ w1, const float* __restrict__ b1,
    const float* __restrict__ w2, const float* __restrict__ b2)
{
    __shared__ float pts[2][PP];
    __shared__ float h1[DE][PP];
    __shared__ __align__(16) float w2sp[80][16];
    __shared__ float w1s[160];
    __shared__ float b1s[16], b2s[16];
    __shared__ float redw[4][16];

    const int tid = threadIdx.x;
    const int t = blockIdx.y, e = blockIdx.x;

    const float2* pin2 = reinterpret_cast<const float2*>(points + (size_t)(t * EE + e) * PP * 2);
    #pragma unroll
    for (int j = 0; j < 4; j++) {
        int p = tid + j * 128;
        float2 v = pin2[p];
        pts[0][p] = v.x; pts[1][p] = v.y;
    }
    for (int i = tid; i < 160; i += 128) w1s[i] = w1[t * 160 + i];
    for (int i = tid; i < 1280; i += 128) w2sp[i % 80][i / 80] = w2[t * 1280 + i];
    if (tid < 16) { b1s[tid] = b1[t * 16 + tid]; b2s[tid] = b2[t * 16 + tid]; }
    __syncthreads();

    // conv1 (packed f32x2, position pairs)
    u64 xp[2][5], yp[2][5];
    #pragma unroll
    for (int pr = 0; pr < 2; pr++) {
        int pA = tid + (2 * pr) * 128;
        int pB = tid + (2 * pr + 1) * 128;
        int pAc = (pA < P1) ? pA : (P1 - 1);
        int pBc = (pB < P1) ? pB : (P1 - 1);
        #pragma unroll
        for (int k = 0; k < 5; k++) {
            xp[pr][k] = pack2(pts[0][pAc + k], pts[0][pBc + k]);
            yp[pr][k] = pack2(pts[1][pAc + k], pts[1][pBc + k]);
        }
    }
    const bool m1 = (tid + 384 < P1);
    #pragma unroll 1
    for (int co = 0; co < 16; co++) {
        float wc[10];
        #pragma unroll
        for (int q = 0; q < 10; q++) wc[q] = w1s[co * 10 + q];
        float bb = b1s[co];
        u64 a0 = pack2(bb, bb), a1 = a0;
        #pragma unroll
        for (int k = 0; k < 5; k++) {
            u64 w = pack2(wc[k], wc[k]);
            fma2(a0, w, xp[0][k]);
            fma2(a1, w, xp[1][k]);
        }
        #pragma unroll
        for (int k = 0; k < 5; k++) {
            u64 w = pack2(wc[5 + k], wc[5 + k]);
            fma2(a0, w, yp[0][k]);
            fma2(a1, w, yp[1][k]);
        }
        float v0, v1, v2, v3;
        unpack2(a0, v0, v1);
        unpack2(a1, v2, v3);
        h1[co][tid]       = fmaxf(v0, 0.f);
        h1[co][tid + 128] = fmaxf(v1, 0.f);
        h1[co][tid + 256] = fmaxf(v2, 0.f);
        if (m1) h1[co][tid + 384] = fmaxf(v3, 0.f);
    }
    __syncthreads();

    // conv2 (packed f32x2, co-pairs) + relu + point sum
    const int p0 = tid, pa = tid + 128, pb = tid + 256;
    const int p3 = (tid + 384 < P2) ? (tid + 384) : (P2 - 1);

    u64 acc[4][8];
    #pragma unroll
    for (int cp = 0; cp < 8; cp++) {
        u64 bi = pack2(b2s[2 * cp], b2s[2 * cp + 1]);
        acc[0][cp] = bi; acc[1][cp] = bi; acc[2][cp] = bi; acc[3][cp] = bi;
    }

    #pragma unroll 1
    for (int ci = 0; ci < 16; ci++) {
        const float* hrow = h1[ci];
        const u64* wrow = reinterpret_cast<const u64*>(&w2sp[ci * 5][0]);
        #pragma unroll
        for (int k = 0; k < 5; k++) {
            float h0 = hrow[p0 + k], h1v = hrow[pa + k], h2 = hrow[pb + k], h3 = hrow[p3 + k];
            u64 hp0 = pack2(h0, h0);
            u64 hp1 = pack2(h1v, h1v);
            u64 hp2 = pack2(h2, h2);
            u64 hp3 = pack2(h3, h3);
            #pragma unroll
            for (int cp = 0; cp < 8; cp++) {
                u64 w = wrow[k * 8 + cp];
                fma2(acc[0][cp], w, hp0);
                fma2(acc[1][cp], w, hp1);
                fma2(acc[2][cp], w, hp2);
                fma2(acc[3][cp], w, hp3);
            }
        }
    }

    float s16[16];
    const bool m3 = (tid + 384 < P2);
    #pragma unroll
    for (int cp = 0; cp < 8; cp++) {
        float a0, c0, a1, c1, a2, c2, a3, c3;
        unpack2(acc[0][cp], a0, c0);
        unpack2(acc[1][cp], a1, c1);
        unpack2(acc[2][cp], a2, c2);
        unpack2(acc[3][cp], a3, c3);
        float se = fmaxf(a0, 0.f) + fmaxf(a1, 0.f) + fmaxf(a2, 0.f);
        float so = fmaxf(c0, 0.f) + fmaxf(c1, 0.f) + fmaxf(c2, 0.f);
        if (m3) { se += fmaxf(a3, 0.f); so += fmaxf(c3, 0.f); }
        s16[2 * cp] = se; s16[2 * cp + 1] = so;
    }

    #pragma unroll
    for (int co = 0; co < 16; co++) {
        float v = s16[co];
        #pragma unroll
        for (int o = 16; o > 0; o >>= 1) v += __shfl_xor_sync(0xffffffffu, v, o);
        s16[co] = v;
    }
    const int lane = tid & 31, warp = tid >> 5;
    if (lane == 0) {
        #pragma unroll
        for (int co = 0; co < 16; co++) redw[warp][co] = s16[co];
    }
    __syncthreads();
    if (tid < 16)
        d_elem[(size_t)(t * EE + e) * 16 + tid] =
            redw[0][tid] + redw[1][tid] + redw[2][tid] + redw[3][tid];
}

// ---------------- K2: fused tail (everything after conv) ----------------
// grid 128 (t = blk>>5, chunk = blk&31; 64 e's per block), block 256
__global__ __launch_bounds__(256) void k_tail(
    const float* __restrict__ A1, const float* __restrict__ B1,
    const float* __restrict__ A2, const float* __restrict__ B2,
    const float* __restrict__ Aout, const float* __restrict__ Wm,
    const float* __restrict__ bm, float* __restrict__ out)
{
    __shared__ __align__(8) float g1T[128][66];   // [feature h][ei 0..63]
    union Shm {
        struct { float C1s[16][128]; float elems[64][16]; } ph1;
        float C2q[16][128];
        float gfs[512];
    };
    __shared__ Shm u;
    __shared__ float r[256];
    __shared__ float s0s[16];
    __shared__ float s1s[128];

    const int tid = threadIdx.x;
    const int blk = blockIdx.x;
    const int t = blk >> 5, chunk = blk & 31;
    const int e0 = chunk * 64;
    const int h = tid & 127, half = tid >> 7;
    const int tb = t * 16384;
    const unsigned NB = 128;

    // ===== Phase A: s0 partials + gmax zero =====
    {
        const int d = tid & 15, grp = tid >> 4;   // 16 groups of 4 e's
        float acc = 0.f;
        #pragma unroll
        for (int i = 0; i < 4; i++)
            acc += d_elem[(size_t)(t * EE + e0 + grp + 16 * i) * 16 + d];
        r[tid] = acc; __syncthreads();
        if (tid < 128) r[tid] += r[tid + 128];
        __syncthreads();
        if (tid < 64) r[tid] += r[tid + 64];
        __syncthreads();
        if (tid < 32) r[tid] += r[tid + 32];
        __syncthreads();
        if (tid < 16) d_s0p[(t * 32 + chunk) * 16 + tid] = r[tid] + r[tid + 16];
        if (chunk == 0 && tid < 128) d_gmax[t * 128 + tid] = 0;
    }
    gbar(NB);

    // ===== Phase B: g1 for this block's 64 e's (into smem) + s1 partials =====
    if (tid < 16) {
        float s = 0.f;
        #pragma unroll
        for (int b = 0; b < 32; b++) s += d_s0p[(t * 32 + b) * 16 + tid];
        s0s[tid] = s;
    }
    for (int i = tid; i < 2048; i += 256)
        u.ph1.C1s[i >> 7][i & 127] = A1[t * 2048 + i] - B1[t * 2048 + i];
    for (int i = tid; i < 1024; i += 256)
        u.ph1.elems[i >> 4][i & 15] = d_elem[(size_t)(t * EE + e0) * 16 + i];
    __syncthreads();

    float c1r[16];
    #pragma unroll
    for (int d = 0; d < 16; d++) c1r[d] = u.ph1.C1s[d][h];
    float sbl1 = 0.f;
    #pragma unroll
    for (int d = 0; d < 16; d++)
        sbl1 = fmaf(s0s[d], B1[t * 2048 + d * 128 + h], sbl1);

    {
        float acc = 0.f;
        const int eib = half * 32;
        #pragma unroll 4
        for (int ei = 0; ei < 32; ei++) {
            float v = sbl1;
            #pragma unroll
            for (int d = 0; d < 16; d++) v = fmaf(u.ph1.elems[eib + ei][d], c1r[d], v);
            v = fmaxf(v, 0.f);
            g1T[h][eib + ei] = v;
            acc += v;
        }
        d_s1p[(t * 64 + chunk * 2 + half) * 128 + h] = acc;
    }
    gbar(NB);

    // ===== Phase C: layer2 GEMM + max -> d_gmax =====
    if (tid < 128) {
        float s = 0.f;
        #pragma unroll 4
        for (int j = 0; j < 64; j++) s += d_s1p[(t * 64 + j) * 128 + tid];
        s1s[tid] = s;
    }
    __syncthreads();

    float sb = 0.f;
    #pragma unroll 4
    for (int d = 0; d < 128; d++)
        sb = fmaf(s1s[d], B2[tb + d * 128 + h], sb);

    u64 acc2[16];
    #pragma unroll
    for (int pr = 0; pr < 16; pr++) acc2[pr] = pack2(sb, sb);

    for (int q = 0; q < 8; q++) {
        const int d0 = q * 16;
        __syncthreads();
        for (int i = tid; i < 2048; i += 256) {
            int d = i >> 7, hh = i & 127;
            u.C2q[d][hh] = A2[tb + (d0 + d) * 128 + hh] - B2[tb + (d0 + d) * 128 + hh];
        }
        __syncthreads();
        #pragma unroll 4
        for (int dd = 0; dd < 16; dd++) {
            float c = u.C2q[dd][h];
            u64 cp = pack2(c, c);
            const u64* grow = reinterpret_cast<const u64*>(&g1T[d0 + dd][half * 32]);
            #pragma unroll
            for (int pr = 0; pr < 16; pr++) fma2(acc2[pr], grow[pr], cp);
        }
    }

    {
        float m = 0.f;   // relu floor == max identity
        #pragma unroll
        for (int pr = 0; pr < 16; pr++) {
            float a, b;
            unpack2(acc2[pr], a, b);
            m = fmaxf(m, fmaxf(a, b));
        }
        atomicMax(&d_gmax[t * 128 + h], __float_as_int(m));
    }
    gbar(NB);

    // ===== Phase D: gf[t] = gmax[t] @ Aout[t]  (blocks chunk==0) =====
    if (chunk == 0) {
        if (tid < 128) s1s[tid] = __int_as_float(d_gmax[t * 128 + tid]);
        __syncthreads();
        if (tid < 128) {
            float a = 0.f;
            #pragma unroll 4
            for (int hh = 0; hh < 128; hh++)
                a = fmaf(s1s[hh], Aout[t * 16384 + hh * 128 + tid], a);
            d_gf[t * 128 + tid] = a;
        }
    }
    gbar(NB);

    // ===== Phase E: final matmul partials (blocks 0..7) =====
    if (blk < 8) {
        for (int i = tid; i < 512; i += 256) u.gfs[i] = d_gf[i];
        __syncthreads();
        float a = 0.f;
        const int i0 = blk * 64;
        #pragma unroll 8
        for (int i = 0; i < 64; i++)
            a = fmaf(u.gfs[i0 + i], Wm[(i0 + i) * 256 + tid], a);
        d_fpart[blk * 256 + tid] = a;
    }
    gbar(NB);

    // ===== Phase F: combine (block 0) =====
    if (blk == 0) {
        float a = bm[tid];
        #pragma unroll
        for (int b = 0; b < 8; b++) a += d_fpart[b * 256 + tid];
        out[tid] = a;
    }
}

// ---------------- launch ----------------
extern "C" void kernel_launch(void* const* d_in, const int* in_sizes, int n_in,
                              void* d_out, int out_size)
{
    const float* points = (const float*)d_in[0];
    const float* w1     = (const float*)d_in[1];
    const float* b1     = (const float*)d_in[2];
    const float* w2     = (const float*)d_in[3];
    const float* b2     = (const float*)d_in[4];
    const float* A1     = (const float*)d_in[5];
    const float* B1     = (const float*)d_in[6];
    const float* A2     = (const float*)d_in[7];
    const float* B2     = (const float*)d_in[8];
    const float* Aout   = (const float*)d_in[9];
    const float* Wm     = (const float*)d_in[10];
    const float* bm     = (const float*)d_in[11];
    float* out = (float*)d_out;

    k_conv<<<dim3(EE, TT), 128>>>(points, w1, b1, w2, b2);
    k_tail<<<128, 256>>>(A1, B1, A2, B2, Aout, Wm, bm, out);
}

// round 8
// speedup vs baseline: 1.2461x; 1.0834x over previous
#include <cuda_runtime.h>
#include <cuda_bf16.h>

#define TT 4
#define EE 2048
#define PP 512
#define DE 16
#define DH 128
#define P1 508   // P-K+1
#define P2 504   // P-2K+2

typedef unsigned long long u64;

// ---------------- scratch (device globals) ----------------
__device__ float d_elem[TT * EE * DE];        // [t][e][16]
__device__ float d_s0p[TT * 16 * 16];         // s0 partials [t][chunk][16]
__device__ float d_g1[TT * EE * DH];          // [t][e][128] (L2-resident)
__device__ float d_s1p[TT * 64 * DH];         // s1 partials [t][chunk][128]
__device__ int   d_gmax[TT * DH];             // float bits, >= 0
__device__ float d_fpart[8 * 256];

// ---------------- f32x2 helpers ----------------
__device__ __forceinline__ u64 pack2(float a, float b) {
    u64 r; asm("mov.b64 %0, {%1, %2};" : "=l"(r) : "f"(a), "f"(b)); return r;
}
__device__ __forceinline__ void unpack2(u64 v, float& a, float& b) {
    asm("mov.b64 {%0, %1}, %2;" : "=f"(a), "=f"(b) : "l"(v));
}
__device__ __forceinline__ void fma2(u64& d, u64 a, u64 b) {
    asm("fma.rn.f32x2 %0, %1, %2, %0;" : "+l"(d) : "l"(a), "l"(b));
}

// ---------------- K1: conv1 + conv2 + point-sum -> elem_latent ----------------
// grid (E, T), block 128  (unchanged — near f32x2 issue floor)
__global__ __launch_bounds__(128) void k_conv(
    const float* __restrict__ points,
    const float* __restrict__ w1, const float* __restrict__ b1,
    const float* __restrict__ w2, const float* __restrict__ b2)
{
    __shared__ float pts[2][PP];
    __shared__ float h1[DE][PP];
    __shared__ __align__(16) float w2sp[80][16];
    __shared__ float w1s[160];
    __shared__ float b1s[16], b2s[16];
    __shared__ float redw[4][16];

    const int tid = threadIdx.x;
    const int t = blockIdx.y, e = blockIdx.x;

    const float2* pin2 = reinterpret_cast<const float2*>(points + (size_t)(t * EE + e) * PP * 2);
    #pragma unroll
    for (int j = 0; j < 4; j++) {
        int p = tid + j * 128;
        float2 v = pin2[p];
        pts[0][p] = v.x; pts[1][p] = v.y;
    }
    for (int i = tid; i < 160; i += 128) w1s[i] = w1[t * 160 + i];
    for (int i = tid; i < 1280; i += 128) w2sp[i % 80][i / 80] = w2[t * 1280 + i];
    if (tid < 16) { b1s[tid] = b1[t * 16 + tid]; b2s[tid] = b2[t * 16 + tid]; }
    __syncthreads();

    u64 xp[2][5], yp[2][5];
    #pragma unroll
    for (int pr = 0; pr < 2; pr++) {
        int pA = tid + (2 * pr) * 128;
        int pB = tid + (2 * pr + 1) * 128;
        int pAc = (pA < P1) ? pA : (P1 - 1);
        int pBc = (pB < P1) ? pB : (P1 - 1);
        #pragma unroll
        for (int k = 0; k < 5; k++) {
            xp[pr][k] = pack2(pts[0][pAc + k], pts[0][pBc + k]);
            yp[pr][k] = pack2(pts[1][pAc + k], pts[1][pBc + k]);
        }
    }
    const bool m1 = (tid + 384 < P1);
    #pragma unroll 1
    for (int co = 0; co < 16; co++) {
        float wc[10];
        #pragma unroll
        for (int q = 0; q < 10; q++) wc[q] = w1s[co * 10 + q];
        float bb = b1s[co];
        u64 a0 = pack2(bb, bb), a1 = a0;
        #pragma unroll
        for (int k = 0; k < 5; k++) {
            u64 w = pack2(wc[k], wc[k]);
            fma2(a0, w, xp[0][k]);
            fma2(a1, w, xp[1][k]);
        }
        #pragma unroll
        for (int k = 0; k < 5; k++) {
            u64 w = pack2(wc[5 + k], wc[5 + k]);
            fma2(a0, w, yp[0][k]);
            fma2(a1, w, yp[1][k]);
        }
        float v0, v1, v2, v3;
        unpack2(a0, v0, v1);
        unpack2(a1, v2, v3);
        h1[co][tid]       = fmaxf(v0, 0.f);
        h1[co][tid + 128] = fmaxf(v1, 0.f);
        h1[co][tid + 256] = fmaxf(v2, 0.f);
        if (m1) h1[co][tid + 384] = fmaxf(v3, 0.f);
    }
    __syncthreads();

    const int p0 = tid, pa = tid + 128, pb = tid + 256;
    const int p3 = (tid + 384 < P2) ? (tid + 384) : (P2 - 1);

    u64 acc[4][8];
    #pragma unroll
    for (int cp = 0; cp < 8; cp++) {
        u64 bi = pack2(b2s[2 * cp], b2s[2 * cp + 1]);
        acc[0][cp] = bi; acc[1][cp] = bi; acc[2][cp] = bi; acc[3][cp] = bi;
    }

    #pragma unroll 1
    for (int ci = 0; ci < 16; ci++) {
        const float* hrow = h1[ci];
        const u64* wrow = reinterpret_cast<const u64*>(&w2sp[ci * 5][0]);
        #pragma unroll
        for (int k = 0; k < 5; k++) {
            float h0 = hrow[p0 + k], h1v = hrow[pa + k], h2 = hrow[pb + k], h3 = hrow[p3 + k];
            u64 hp0 = pack2(h0, h0);
            u64 hp1 = pack2(h1v, h1v);
            u64 hp2 = pack2(h2, h2);
            u64 hp3 = pack2(h3, h3);
            #pragma unroll
            for (int cp = 0; cp < 8; cp++) {
                u64 w = wrow[k * 8 + cp];
                fma2(acc[0][cp], w, hp0);
                fma2(acc[1][cp], w, hp1);
                fma2(acc[2][cp], w, hp2);
                fma2(acc[3][cp], w, hp3);
            }
        }
    }

    float s16[16];
    const bool m3 = (tid + 384 < P2);
    #pragma unroll
    for (int cp = 0; cp < 8; cp++) {
        float a0, c0, a1, c1, a2, c2, a3, c3;
        unpack2(acc[0][cp], a0, c0);
        unpack2(acc[1][cp], a1, c1);
        unpack2(acc[2][cp], a2, c2);
        unpack2(acc[3][cp], a3, c3);
        float se = fmaxf(a0, 0.f) + fmaxf(a1, 0.f) + fmaxf(a2, 0.f);
        float so = fmaxf(c0, 0.f) + fmaxf(c1, 0.f) + fmaxf(c2, 0.f);
        if (m3) { se += fmaxf(a3, 0.f); so += fmaxf(c3, 0.f); }
        s16[2 * cp] = se; s16[2 * cp + 1] = so;
    }

    #pragma unroll
    for (int co = 0; co < 16; co++) {
        float v = s16[co];
        #pragma unroll
        for (int o = 16; o > 0; o >>= 1) v += __shfl_xor_sync(0xffffffffu, v, o);
        s16[co] = v;
    }
    const int lane = tid & 31, warp = tid >> 5;
    if (lane == 0) {
        #pragma unroll
        for (int co = 0; co < 16; co++) redw[warp][co] = s16[co];
    }
    __syncthreads();
    if (tid < 16)
        d_elem[(size_t)(t * EE + e) * 16 + tid] =
            redw[0][tid] + redw[1][tid] + redw[2][tid] + redw[3][tid];
}

// ---------------- K2: s0 partials (+zero gmax)  grid (16, T), block 256 ----------------
__global__ __launch_bounds__(256) void k_s0p() {
    const int t = blockIdx.y, chunk = blockIdx.x, tid = threadIdx.x;
    const int d = tid & 15, grp = tid >> 4;   // 16 groups x 8 e's
    const int e0 = chunk * 128;
    float acc = 0.f;
    #pragma unroll
    for (int i = 0; i < 8; i++)
        acc += d_elem[(size_t)(t * EE + e0 + grp + 16 * i) * 16 + d];
    __shared__ float r[256];
    r[tid] = acc; __syncthreads();
    if (tid < 128) r[tid] += r[tid + 128];
    __syncthreads();
    if (tid < 64) r[tid] += r[tid + 64];
    __syncthreads();
    if (tid < 32) r[tid] += r[tid + 32];
    __syncthreads();
    if (tid < 16) d_s0p[(t * 16 + chunk) * 16 + tid] = r[tid] + r[tid + 16];
    if (chunk == 0 && tid < 128) d_gmax[t * 128 + tid] = 0;
}

// ---------------- K3: layer1 -> d_g1 + s1 partials  grid (64, T), block 256 ----------------
__global__ __launch_bounds__(256) void k_l1(
    const float* __restrict__ A1, const float* __restrict__ B1)
{
    __shared__ float C1s[16][128];
    __shared__ float elems[32][16];
    __shared__ float r[256];
    __shared__ float s0s[16];

    const int tid = threadIdx.x, t = blockIdx.y, chunk = blockIdx.x;
    const int e0 = chunk * 32;
    const int h = tid & 127, half = tid >> 7;

    for (int i = tid; i < 512; i += 256)
        elems[i >> 4][i & 15] = d_elem[(size_t)(t * EE + e0) * 16 + i];
    for (int i = tid; i < 2048; i += 256)
        C1s[i >> 7][i & 127] = A1[t * 2048 + i] - B1[t * 2048 + i];
    if (tid < 16) {
        float s = 0.f;
        #pragma unroll
        for (int b = 0; b < 16; b++) s += d_s0p[(t * 16 + b) * 16 + tid];
        s0s[tid] = s;
    }
    __syncthreads();

    float c1r[16];
    #pragma unroll
    for (int d = 0; d < 16; d++) c1r[d] = C1s[d][h];
    float sbl1 = 0.f;
    #pragma unroll
    for (int d = 0; d < 16; d++)
        sbl1 = fmaf(s0s[d], B1[t * 2048 + d * 128 + h], sbl1);

    float accs = 0.f;
    const int eib = half * 16;
    #pragma unroll 4
    for (int ei = 0; ei < 16; ei++) {
        float v = sbl1;
        #pragma unroll
        for (int d = 0; d < 16; d++) v = fmaf(elems[eib + ei][d], c1r[d], v);
        v = fmaxf(v, 0.f);
        d_g1[(size_t)(t * EE + e0 + eib + ei) * 128 + h] = v;
        accs += v;
    }
    r[tid] = accs;
    __syncthreads();
    if (tid < 128)
        d_s1p[(t * 64 + chunk) * 128 + tid] = r[tid] + r[tid + 128];
}

// ---------------- K4: layer2 GEMM + max  grid (64, T), block 256 ----------------
__global__ __launch_bounds__(256) void k_l2(
    const float* __restrict__ A2, const float* __restrict__ B2)
{
    __shared__ __align__(8) float g1T[128][34];   // [feature d][ei 0..31]
    __shared__ float C2q[2][16][128];
    __shared__ float r[256];
    __shared__ float s1s[128];

    const int tid = threadIdx.x, t = blockIdx.y, chunk = blockIdx.x;
    const int e0 = chunk * 32;
    const int h = tid & 127, half = tid >> 7;
    const int tb = t * 16384;

    // prefetch first C2 slab early (latency overlap with staging below)
    float pa_[8], pb_[8];
    #pragma unroll
    for (int k = 0; k < 8; k++) {
        int idx = tid + k * 256;
        pa_[k] = A2[tb + idx];
        pb_[k] = B2[tb + idx];
    }

    // s1 combine (64 partials)
    {
        float a = 0.f;
        #pragma unroll 4
        for (int s = 0; s < 32; s++)
            a += d_s1p[(t * 64 + half * 32 + s) * 128 + h];
        r[tid] = a;
    }

    // g1 tile load (transposed into smem)
    for (int i = tid; i < 4096; i += 256) {
        int ei = i >> 7, hh = i & 127;
        g1T[hh][ei] = d_g1[(size_t)(t * EE + e0 + ei) * 128 + hh];
    }
    __syncthreads();
    if (tid < 128) s1s[tid] = r[tid] + r[tid + 128];
    __syncthreads();

    u64 acc2[8];
    #pragma unroll
    for (int pr = 0; pr < 8; pr++) acc2[pr] = 0ull;
    float sbp = 0.f;

    #pragma unroll 1
    for (int q = 0; q < 8; q++) {
        const int buf = q & 1;
        #pragma unroll
        for (int k = 0; k < 8; k++) {
            int d = 2 * k + half;
            sbp = fmaf(s1s[q * 16 + d], pb_[k], sbp);
            C2q[buf][d][h] = pa_[k] - pb_[k];
        }
        __syncthreads();
        if (q < 7) {
            const int base = tb + (q + 1) * 16 * 128;
            #pragma unroll
            for (int k = 0; k < 8; k++) {
                int idx = tid + k * 256;
                pa_[k] = A2[base + idx];
                pb_[k] = B2[base + idx];
            }
        }
        #pragma unroll 4
        for (int dd = 0; dd < 16; dd++) {
            float c = C2q[buf][dd][h];
            u64 cp = pack2(c, c);
            const u64* grow = reinterpret_cast<const u64*>(&g1T[q * 16 + dd][half * 16]);
            #pragma unroll
            for (int pr = 0; pr < 8; pr++) fma2(acc2[pr], grow[pr], cp);
        }
        __syncthreads();
    }

    // combine sb halves (even/odd d parity)
    r[tid] = sbp;
    __syncthreads();
    const float sb = r[h] + r[h + 128];

    float m = 0.f;   // relu floor == max identity
    #pragma unroll
    for (int pr = 0; pr < 8; pr++) {
        float a, b;
        unpack2(acc2[pr], a, b);
        m = fmaxf(m, fmaxf(a + sb, b + sb));
    }
    atomicMax(&d_gmax[t * 128 + h], __float_as_int(m));
}

// ---------------- K5: gf + final matmul partials  grid 8, block 256 ----------------
__global__ __launch_bounds__(256) void k_gfw(const float* __restrict__ Aout,
                                             const float* __restrict__ Wm)
{
    __shared__ float gv[512];
    __shared__ float gfs[64];
    __shared__ float r[256];
    const int tid = threadIdx.x, blk = blockIdx.x;

    for (int i = tid; i < 512; i += 256) gv[i] = __int_as_float(d_gmax[i]);
    __syncthreads();

    const int j = tid >> 2, sub = tid & 3;
    const int gi = blk * 64 + j;          // global gf index = t*128 + o
    const int t2 = gi >> 7, o = gi & 127;
    float a = 0.f;
    #pragma unroll 4
    for (int k = 0; k < 32; k++)
        a = fmaf(gv[t2 * 128 + sub * 32 + k],
                 Aout[t2 * 16384 + (sub * 32 + k) * 128 + o], a);
    r[tid] = a;
    __syncthreads();
    if (sub == 0) gfs[j] = r[tid] + r[tid + 1] + r[tid + 2] + r[tid + 3];
    __syncthreads();

    float acc = 0.f;
    const int i0 = blk * 64;
    #pragma unroll 8
    for (int i = 0; i < 64; i++)
        acc = fmaf(gfs[i], Wm[(i0 + i) * 256 + tid], acc);
    d_fpart[blk * 256 + tid] = acc;
}

// ---------------- K6: combine  grid 1, block 256 ----------------
__global__ void k_fin2(const float* __restrict__ bm, float* __restrict__ out) {
    const int tid = threadIdx.x;
    float a = bm[tid];
    #pragma unroll
    for (int b = 0; b < 8; b++) a += d_fpart[b * 256 + tid];
    out[tid] = a;
}

// ---------------- launch ----------------
extern "C" void kernel_launch(void* const* d_in, const int* in_sizes, int n_in,
                              void* d_out, int out_size)
{
    const float* points = (const float*)d_in[0];
    const float* w1     = (const float*)d_in[1];
    const float* b1     = (const float*)d_in[2];
    const float* w2     = (const float*)d_in[3];
    const float* b2     = (const float*)d_in[4];
    const float* A1     = (const float*)d_in[5];
    const float* B1     = (const float*)d_in[6];
    const float* A2     = (const float*)d_in[7];
    const float* B2     = (const float*)d_in[8];
    const float* Aout   = (const float*)d_in[9];
    const float* Wm     = (const float*)d_in[10];
    const float* bm     = (const float*)d_in[11];
    float* out = (float*)d_out;

    k_conv<<<dim3(EE, TT), 128>>>(points, w1, b1, w2, b2);
    k_s0p<<<dim3(16, TT), 256>>>();
    k_l1<<<dim3(64, TT), 256>>>(A1, B1);
    k_l2<<<dim3(64, TT), 256>>>(A2, B2);
    k_gfw<<<8, 256>>>(Aout, Wm);
    k_fin2<<<1, 256>>>(bm, out);
}

// round 9
// speedup vs baseline: 1.7654x; 1.4167x over previous
#include <cuda_runtime.h>
#include <cuda_bf16.h>

#define TT 4
#define EE 2048
#define PP 512
#define DE 16
#define DH 128
#define P1 508   // P-K+1
#define P2 504   // P-2K+2

typedef unsigned long long u64;

// ---------------- scratch (device globals) ----------------
__device__ float d_elem[TT * EE * DE];        // [t][e][16]
__device__ float d_s0p[TT * 16 * 16];         // s0 partials [t][chunk][16]
__device__ float d_g1[TT * EE * DH];          // [t][e][128] (L2-resident)
__device__ float d_s1p[TT * 64 * DH];         // s1 partials [t][chunk][128]
__device__ int   d_gmax[TT * DH];             // float bits, >= 0
__device__ float d_fpart[8 * 256];

// ---------------- f32x2 helpers ----------------
__device__ __forceinline__ u64 pack2(float a, float b) {
    u64 r; asm("mov.b64 %0, {%1, %2};" : "=l"(r) : "f"(a), "f"(b)); return r;
}
__device__ __forceinline__ void unpack2(u64 v, float& a, float& b) {
    asm("mov.b64 {%0, %1}, %2;" : "=f"(a), "=f"(b) : "l"(v));
}
__device__ __forceinline__ void fma2(u64& d, u64 a, u64 b) {
    asm("fma.rn.f32x2 %0, %1, %2, %0;" : "+l"(d) : "l"(a), "l"(b));
}

// ---------------- bf16 mma m16n8k16 (A row, B col, fp32 acc) ----------------
__device__ __forceinline__ void mma_bf16(float* c,
    unsigned a0, unsigned a1, unsigned a2, unsigned a3,
    unsigned b0, unsigned b1)
{
    asm volatile(
        "mma.sync.aligned.m16n8k16.row.col.f32.bf16.bf16.f32 "
        "{%0,%1,%2,%3}, {%4,%5,%6,%7}, {%8,%9}, {%0,%1,%2,%3};"
        : "+f"(c[0]), "+f"(c[1]), "+f"(c[2]), "+f"(c[3])
        : "r"(a0), "r"(a1), "r"(a2), "r"(a3), "r"(b0), "r"(b1));
}

// ---------------- K1: conv1 (f32x2) + conv2 (bf16 HMMA split) ----------------
// grid (E, T), block 128
__global__ __launch_bounds__(128) void k_conv(
    const float* __restrict__ points,
    const float* __restrict__ w1, const float* __restrict__ b1,
    const float* __restrict__ w2, const float* __restrict__ b2)
{
    // h1 transposed [p][ci], split big/residual bf16, row stride 18 bf16 (9 words)
    __shared__ __align__(16) __nv_bfloat16 h1b[520 * 18];
    __shared__ __align__(16) __nv_bfloat16 h1r[520 * 18];
    __shared__ float pts[2][PP];
    __shared__ __align__(4) __nv_bfloat16 w2b[1280];   // [(co*5+s)*16 + ci]
    __shared__ __align__(4) __nv_bfloat16 w2r[1280];
    __shared__ float w1s[160];
    __shared__ float b1s[16], b2s[16];
    __shared__ float redw[4][16];

    const int tid = threadIdx.x;
    const int t = blockIdx.y, e = blockIdx.x;

    // ---- stage inputs ----
    const float2* pin2 = reinterpret_cast<const float2*>(points + (size_t)(t * EE + e) * PP * 2);
    #pragma unroll
    for (int j = 0; j < 4; j++) {
        int p = tid + j * 128;
        float2 v = pin2[p];
        pts[0][p] = v.x; pts[1][p] = v.y;
    }
    for (int i = tid; i < 160; i += 128) w1s[i] = w1[t * 160 + i];
    // split W2 into bf16 big + residual, layout [(co*5+s)*16 + ci]
    for (int i = tid; i < 1280; i += 128) {
        float v = w2[t * 1280 + i];
        int co = i / 80, rem = i % 80, ci = rem / 5, s = rem % 5;
        __nv_bfloat16 b = __float2bfloat16(v);
        float r = v - __bfloat162float(b);
        w2b[(co * 5 + s) * 16 + ci] = b;
        w2r[(co * 5 + s) * 16 + ci] = __float2bfloat16(r);
    }
    if (tid < 16) { b1s[tid] = b1[t * 16 + tid]; b2s[tid] = b2[t * 16 + tid]; }
    __syncthreads();

    // ---- conv1 (packed f32x2, position pairs) -> h1 transposed bf16 split ----
    u64 xp[2][5], yp[2][5];
    #pragma unroll
    for (int pr = 0; pr < 2; pr++) {
        int pA = tid + (2 * pr) * 128;
        int pB = tid + (2 * pr + 1) * 128;
        int pAc = (pA < P1) ? pA : (P1 - 1);
        int pBc = (pB < P1) ? pB : (P1 - 1);
        #pragma unroll
        for (int k = 0; k < 5; k++) {
            xp[pr][k] = pack2(pts[0][pAc + k], pts[0][pBc + k]);
            yp[pr][k] = pack2(pts[1][pAc + k], pts[1][pBc + k]);
        }
    }
    const bool m1 = (tid + 384 < P1);
    #pragma unroll 1
    for (int co = 0; co < 16; co++) {
        float wc[10];
        #pragma unroll
        for (int q = 0; q < 10; q++) wc[q] = w1s[co * 10 + q];
        float bb = b1s[co];
        u64 a0 = pack2(bb, bb), a1 = a0;
        #pragma unroll
        for (int k = 0; k < 5; k++) {
            u64 w = pack2(wc[k], wc[k]);
            fma2(a0, w, xp[0][k]);
            fma2(a1, w, xp[1][k]);
        }
        #pragma unroll
        for (int k = 0; k < 5; k++) {
            u64 w = pack2(wc[5 + k], wc[5 + k]);
            fma2(a0, w, yp[0][k]);
            fma2(a1, w, yp[1][k]);
        }
        float v0, v1, v2, v3;
        unpack2(a0, v0, v1);
        unpack2(a1, v2, v3);
        v0 = fmaxf(v0, 0.f); v1 = fmaxf(v1, 0.f);
        v2 = fmaxf(v2, 0.f); v3 = fmaxf(v3, 0.f);
        // store bf16 big + residual, transposed layout [p*18 + co]
        {
            __nv_bfloat16 b0 = __float2bfloat16(v0);
            h1b[tid * 18 + co] = b0;
            h1r[tid * 18 + co] = __float2bfloat16(v0 - __bfloat162float(b0));
            __nv_bfloat16 b1v = __float2bfloat16(v1);
            h1b[(tid + 128) * 18 + co] = b1v;
            h1r[(tid + 128) * 18 + co] = __float2bfloat16(v1 - __bfloat162float(b1v));
            __nv_bfloat16 b2v = __float2bfloat16(v2);
            h1b[(tid + 256) * 18 + co] = b2v;
            h1r[(tid + 256) * 18 + co] = __float2bfloat16(v2 - __bfloat162float(b2v));
            if (m1) {
                __nv_bfloat16 b3v = __float2bfloat16(v3);
                h1b[(tid + 384) * 18 + co] = b3v;
                h1r[(tid + 384) * 18 + co] = __float2bfloat16(v3 - __bfloat162float(b3v));
            }
        }
    }
    __syncthreads();

    // ---- conv2 via bf16 HMMA: C[16co x 8p] tiles, 5 shifts accumulated ----
    // warp wrp handles n-blocks nb = wrp + 4*i, i = 0..15 (63 blocks total)
    const int lane = tid & 31, wrp = tid >> 5;
    const int g = lane >> 2, tq = lane & 3;

    float acc[16][4];
    #pragma unroll
    for (int i = 0; i < 16; i++) {
        acc[i][0] = 0.f; acc[i][1] = 0.f; acc[i][2] = 0.f; acc[i][3] = 0.f;
    }

    const unsigned* h1b32 = reinterpret_cast<const unsigned*>(h1b);
    const unsigned* h1r32 = reinterpret_cast<const unsigned*>(h1r);
    const unsigned* w2b32 = reinterpret_cast<const unsigned*>(w2b);
    const unsigned* w2r32 = reinterpret_cast<const unsigned*>(w2r);

    #pragma unroll
    for (int s = 0; s < 5; s++) {
        // A fragments (W big + residual) for this shift
        const int awl = (g * 5 + s) * 8 + tq;
        const int awh = ((g + 8) * 5 + s) * 8 + tq;
        unsigned ab0 = w2b32[awl],     ab1 = w2b32[awh];
        unsigned ab2 = w2b32[awl + 4], ab3 = w2b32[awh + 4];
        unsigned ar0 = w2r32[awl],     ar1 = w2r32[awh];
        unsigned ar2 = w2r32[awl + 4], ar3 = w2r32[awh + 4];
        #pragma unroll
        for (int i = 0; i < 16; i++) {
            int nb = wrp + 4 * i;
            if (nb >= 63) break;
            int pw = (nb * 8 + g + s) * 9 + tq;   // word index into h1 row
            unsigned bb0 = h1b32[pw], bb1 = h1b32[pw + 4];
            unsigned br0 = h1r32[pw], br1 = h1r32[pw + 4];
            mma_bf16(acc[i], ab0, ab1, ab2, ab3, bb0, bb1);
            mma_bf16(acc[i], ab0, ab1, ab2, ab3, br0, br1);
            mma_bf16(acc[i], ar0, ar1, ar2, ar3, bb0, bb1);
        }
    }

    // ---- epilogue: bias + relu per position, point-sum ----
    const float b2g = b2s[g], b2g8 = b2s[g + 8];
    float sg = 0.f, sg8 = 0.f;
    #pragma unroll
    for (int i = 0; i < 16; i++) {
        int nb = wrp + 4 * i;
        if (nb >= 63) break;
        sg  += fmaxf(acc[i][0] + b2g, 0.f)  + fmaxf(acc[i][1] + b2g, 0.f);
        sg8 += fmaxf(acc[i][2] + b2g8, 0.f) + fmaxf(acc[i][3] + b2g8, 0.f);
    }
    // quad reduce (lanes sharing g)
    sg  += __shfl_xor_sync(0xffffffffu, sg, 1);
    sg  += __shfl_xor_sync(0xffffffffu, sg, 2);
    sg8 += __shfl_xor_sync(0xffffffffu, sg8, 1);
    sg8 += __shfl_xor_sync(0xffffffffu, sg8, 2);
    if (tq == 0) { redw[wrp][g] = sg; redw[wrp][g + 8] = sg8; }
    __syncthreads();
    if (tid < 16)
        d_elem[(size_t)(t * EE + e) * 16 + tid] =
            redw[0][tid] + redw[1][tid] + redw[2][tid] + redw[3][tid];
}

// ---------------- K2: s0 partials (+zero gmax)  grid (16, T), block 256 ----------------
__global__ __launch_bounds__(256) void k_s0p() {
    const int t = blockIdx.y, chunk = blockIdx.x, tid = threadIdx.x;
    const int d = tid & 15, grp = tid >> 4;   // 16 groups x 8 e's
    const int e0 = chunk * 128;
    float acc = 0.f;
    #pragma unroll
    for (int i = 0; i < 8; i++)
        acc += d_elem[(size_t)(t * EE + e0 + grp + 16 * i) * 16 + d];
    __shared__ float r[256];
    r[tid] = acc; __syncthreads();
    if (tid < 128) r[tid] += r[tid + 128];
    __syncthreads();
    if (tid < 64) r[tid] += r[tid + 64];
    __syncthreads();
    if (tid < 32) r[tid] += r[tid + 32];
    __syncthreads();
    if (tid < 16) d_s0p[(t * 16 + chunk) * 16 + tid] = r[tid] + r[tid + 16];
    if (chunk == 0 && tid < 128) d_gmax[t * 128 + tid] = 0;
}

// ---------------- K3: layer1 -> d_g1 + s1 partials  grid (64, T), block 256 ----------------
__global__ __launch_bounds__(256) void k_l1(
    const float* __restrict__ A1, const float* __restrict__ B1)
{
    __shared__ float C1s[16][128];
    __shared__ float elems[32][16];
    __shared__ float r[256];
    __shared__ float s0s[16];

    const int tid = threadIdx.x, t = blockIdx.y, chunk = blockIdx.x;
    const int e0 = chunk * 32;
    const int h = tid & 127, half = tid >> 7;

    for (int i = tid; i < 512; i += 256)
        elems[i >> 4][i & 15] = d_elem[(size_t)(t * EE + e0) * 16 + i];
    for (int i = tid; i < 2048; i += 256)
        C1s[i >> 7][i & 127] = A1[t * 2048 + i] - B1[t * 2048 + i];
    if (tid < 16) {
        float s = 0.f;
        #pragma unroll
        for (int b = 0; b < 16; b++) s += d_s0p[(t * 16 + b) * 16 + tid];
        s0s[tid] = s;
    }
    __syncthreads();

    float c1r[16];
    #pragma unroll
    for (int d = 0; d < 16; d++) c1r[d] = C1s[d][h];
    float sbl1 = 0.f;
    #pragma unroll
    for (int d = 0; d < 16; d++)
        sbl1 = fmaf(s0s[d], B1[t * 2048 + d * 128 + h], sbl1);

    float accs = 0.f;
    const int eib = half * 16;
    #pragma unroll 4
    for (int ei = 0; ei < 16; ei++) {
        float v = sbl1;
        #pragma unroll
        for (int d = 0; d < 16; d++) v = fmaf(elems[eib + ei][d], c1r[d], v);
        v = fmaxf(v, 0.f);
        d_g1[(size_t)(t * EE + e0 + eib + ei) * 128 + h] = v;
        accs += v;
    }
    r[tid] = accs;
    __syncthreads();
    if (tid < 128)
        d_s1p[(t * 64 + chunk) * 128 + tid] = r[tid] + r[tid + 128];
}

// ---------------- K4: layer2 GEMM + max  grid (64, T), block 256 ----------------
__global__ __launch_bounds__(256) void k_l2(
    const float* __restrict__ A2, const float* __restrict__ B2)
{
    __shared__ __align__(8) float g1T[128][34];   // [feature d][ei 0..31]
    __shared__ float C2q[2][16][128];
    __shared__ float r[256];
    __shared__ float s1s[128];

    const int tid = threadIdx.x, t = blockIdx.y, chunk = blockIdx.x;
    const int e0 = chunk * 32;
    const int h = tid & 127, half = tid >> 7;
    const int tb = t * 16384;

    // prefetch first C2 slab early (latency overlap with staging below)
    float pa_[8], pb_[8];
    #pragma unroll
    for (int k = 0; k < 8; k++) {
        int idx = tid + k * 256;
        pa_[k] = A2[tb + idx];
        pb_[k] = B2[tb + idx];
    }

    // s1 combine (64 partials)
    {
        float a = 0.f;
        #pragma unroll 4
        for (int s = 0; s < 32; s++)
            a += d_s1p[(t * 64 + half * 32 + s) * 128 + h];
        r[tid] = a;
    }

    // g1 tile load (transposed into smem)
    for (int i = tid; i < 4096; i += 256) {
        int ei = i >> 7, hh = i & 127;
        g1T[hh][ei] = d_g1[(size_t)(t * EE + e0 + ei) * 128 + hh];
    }
    __syncthreads();
    if (tid < 128) s1s[tid] = r[tid] + r[tid + 128];
    __syncthreads();

    u64 acc2[8];
    #pragma unroll
    for (int pr = 0; pr < 8; pr++) acc2[pr] = 0ull;
    float sbp = 0.f;

    #pragma unroll 1
    for (int q = 0; q < 8; q++) {
        const int buf = q & 1;
        #pragma unroll
        for (int k = 0; k < 8; k++) {
            int d = 2 * k + half;
            sbp = fmaf(s1s[q * 16 + d], pb_[k], sbp);
            C2q[buf][d][h] = pa_[k] - pb_[k];
        }
        __syncthreads();
        if (q < 7) {
            const int base = tb + (q + 1) * 16 * 128;
            #pragma unroll
            for (int k = 0; k < 8; k++) {
                int idx = tid + k * 256;
                pa_[k] = A2[base + idx];
                pb_[k] = B2[base + idx];
            }
        }
        #pragma unroll 4
        for (int dd = 0; dd < 16; dd++) {
            float c = C2q[buf][dd][h];
            u64 cp = pack2(c, c);
            const u64* grow = reinterpret_cast<const u64*>(&g1T[q * 16 + dd][half * 16]);
            #pragma unroll
            for (int pr = 0; pr < 8; pr++) fma2(acc2[pr], grow[pr], cp);
        }
        __syncthreads();
    }

    // combine sb halves (even/odd d parity)
    r[tid] = sbp;
    __syncthreads();
    const float sb = r[h] + r[h + 128];

    float m = 0.f;   // relu floor == max identity
    #pragma unroll
    for (int pr = 0; pr < 8; pr++) {
        float a, b;
        unpack2(acc2[pr], a, b);
        m = fmaxf(m, fmaxf(a + sb, b + sb));
    }
    atomicMax(&d_gmax[t * 128 + h], __float_as_int(m));
}

// ---------------- K5: gf + final matmul partials  grid 8, block 256 ----------------
__global__ __launch_bounds__(256) void k_gfw(const float* __restrict__ Aout,
                                             const float* __restrict__ Wm)
{
    __shared__ float gv[512];
    __shared__ float gfs[64];
    __shared__ float r[256];
    const int tid = threadIdx.x, blk = blockIdx.x;

    for (int i = tid; i < 512; i += 256) gv[i] = __int_as_float(d_gmax[i]);
    __syncthreads();

    const int j = tid >> 2, sub = tid & 3;
    const int gi = blk * 64 + j;          // global gf index = t*128 + o
    const int t2 = gi >> 7, o = gi & 127;
    float a = 0.f;
    #pragma unroll 4
    for (int k = 0; k < 32; k++)
        a = fmaf(gv[t2 * 128 + sub * 32 + k],
                 Aout[t2 * 16384 + (sub * 32 + k) * 128 + o], a);
    r[tid] = a;
    __syncthreads();
    if (sub == 0) gfs[j] = r[tid] + r[tid + 1] + r[tid + 2] + r[tid + 3];
    __syncthreads();

    float acc = 0.f;
    const int i0 = blk * 64;
    #pragma unroll 8
    for (int i = 0; i < 64; i++)
        acc = fmaf(gfs[i], Wm[(i0 + i) * 256 + tid], acc);
    d_fpart[blk * 256 + tid] = acc;
}

// ---------------- K6: combine  grid 1, block 256 ----------------
__global__ void k_fin2(const float* __restrict__ bm, float* __restrict__ out) {
    const int tid = threadIdx.x;
    float a = bm[tid];
    #pragma unroll
    for (int b = 0; b < 8; b++) a += d_fpart[b * 256 + tid];
    out[tid] = a;
}

// ---------------- launch ----------------
extern "C" void kernel_launch(void* const* d_in, const int* in_sizes, int n_in,
                              void* d_out, int out_size)
{
    const float* points = (const float*)d_in[0];
    const float* w1     = (const float*)d_in[1];
    const float* b1     = (const float*)d_in[2];
    const float* w2     = (const float*)d_in[3];
    const float* b2     = (const float*)d_in[4];
    const float* A1     = (const float*)d_in[5];
    const float* B1     = (const float*)d_in[6];
    const float* A2     = (const float*)d_in[7];
    const float* B2     = (const float*)d_in[8];
    const float* Aout   = (const float*)d_in[9];
    const float* Wm     = (const float*)d_in[10];
    const float* bm     = (const float*)d_in[11];
    float* out = (float*)d_out;

    k_conv<<<dim3(EE, TT), 128>>>(points, w1, b1, w2, b2);
    k_s0p<<<dim3(16, TT), 256>>>();
    k_l1<<<dim3(64, TT), 256>>>(A1, B1);
    k_l2<<<dim3(64, TT), 256>>>(A2, B2);
    k_gfw<<<8, 256>>>(Aout, Wm);
    k_fin2<<<1, 256>>>(bm, out);
}

// round 11
// speedup vs baseline: 1.8958x; 1.0739x over previous
#include <cuda_runtime.h>
#include <cuda_bf16.h>

#define TT 4
#define EE 2048
#define PP 512
#define DE 16
#define DH 128
#define P1 508   // P-K+1
#define P2 504   // P-2K+2

typedef unsigned long long u64;

// ---------------- scratch (device globals) ----------------
__device__ float d_elem[TT * EE * DE];        // [t][e][16]
__device__ float d_s0p[TT * 32 * 16];         // s0 partials [t][chunk][16]
__device__ float d_g1[TT * EE * DH];          // [t][e][128] (L2-resident)
__device__ float d_s1p[TT * 128 * DH];        // s1 partials [t][chunk][128]
__device__ int   d_gmax[TT * DH];             // float bits, >= 0
__device__ float d_fpart[8 * 256];

// ---------------- helpers ----------------
__device__ __forceinline__ u64 pack2(float a, float b) {
    u64 r; asm("mov.b64 %0, {%1, %2};" : "=l"(r) : "f"(a), "f"(b)); return r;
}
__device__ __forceinline__ void unpack2(u64 v, float& a, float& b) {
    asm("mov.b64 {%0, %1}, %2;" : "=f"(a), "=f"(b) : "l"(v));
}
__device__ __forceinline__ void fma2(u64& d, u64 a, u64 b) {
    asm("fma.rn.f32x2 %0, %1, %2, %0;" : "+l"(d) : "l"(a), "l"(b));
}
// pack two floats to bf16x2 word: lo <- first arg, hi <- second
__device__ __forceinline__ unsigned cvt2(float lo, float hi) {
    unsigned r;
    asm("cvt.rn.bf16x2.f32 %0, %1, %2;" : "=r"(r) : "f"(hi), "f"(lo));
    return r;
}

// ---------------- bf16 mma m16n8k16 (A row, B col, fp32 acc) ----------------
__device__ __forceinline__ void mma_bf16(float* c,
    unsigned a0, unsigned a1, unsigned a2, unsigned a3,
    unsigned b0, unsigned b1)
{
    asm volatile(
        "mma.sync.aligned.m16n8k16.row.col.f32.bf16.bf16.f32 "
        "{%0,%1,%2,%3}, {%4,%5,%6,%7}, {%8,%9}, {%0,%1,%2,%3};"
        : "+f"(c[0]), "+f"(c[1]), "+f"(c[2]), "+f"(c[3])
        : "r"(a0), "r"(a1), "r"(a2), "r"(a3), "r"(b0), "r"(b1));
}

// ---------------- K1: conv1 (f32x2, co-pairs) + conv2 (bf16 HMMA split) ----------------
// grid (E, T), block 128
__global__ __launch_bounds__(128) void k_conv(
    const float* __restrict__ points,
    const float* __restrict__ w1, const float* __restrict__ b1,
    const float* __restrict__ w2, const float* __restrict__ b2)
{
    // h1 transposed [p][ci], split big/residual bf16, row stride 18 bf16 (9 words)
    __shared__ __align__(16) __nv_bfloat16 h1b[520 * 18];
    __shared__ __align__(16) __nv_bfloat16 h1r[520 * 18];
    __shared__ float pts[2][PP];
    __shared__ __align__(4) __nv_bfloat16 w2b[1280];   // [(co*5+s)*16 + ci]
    __shared__ __align__(4) __nv_bfloat16 w2r[1280];
    __shared__ float w1s[160];
    __shared__ float b1s[16], b2s[16];
    __shared__ float redw[4][16];

    const int tid = threadIdx.x;
    const int t = blockIdx.y, e = blockIdx.x;

    unsigned* h1b32 = reinterpret_cast<unsigned*>(h1b);
    unsigned* h1r32 = reinterpret_cast<unsigned*>(h1r);

    // ---- stage inputs ----
    const float2* pin2 = reinterpret_cast<const float2*>(points + (size_t)(t * EE + e) * PP * 2);
    #pragma unroll
    for (int j = 0; j < 4; j++) {
        int p = tid + j * 128;
        float2 v = pin2[p];
        pts[0][p] = v.x; pts[1][p] = v.y;
    }
    for (int i = tid; i < 160; i += 128) w1s[i] = w1[t * 160 + i];
    // split W2 into bf16 big + residual, layout [(co*5+s)*16 + ci]
    for (int i = tid; i < 1280; i += 128) {
        float v = w2[t * 1280 + i];
        int co = i / 80, rem = i % 80, ci = rem / 5, s = rem % 5;
        __nv_bfloat16 b = __float2bfloat16(v);
        float r = v - __bfloat162float(b);
        w2b[(co * 5 + s) * 16 + ci] = b;
        w2r[(co * 5 + s) * 16 + ci] = __float2bfloat16(r);
    }
    if (tid < 16) { b1s[tid] = b1[t * 16 + tid]; b2s[tid] = b2[t * 16 + tid]; }
    __syncthreads();

    // ---- conv1 (packed f32x2, position pairs, co-pairs) -> h1 split words ----
    u64 xp[2][5], yp[2][5];
    #pragma unroll
    for (int pr = 0; pr < 2; pr++) {
        int pA = tid + (2 * pr) * 128;
        int pB = tid + (2 * pr + 1) * 128;
        int pAc = (pA < P1) ? pA : (P1 - 1);
        int pBc = (pB < P1) ? pB : (P1 - 1);
        #pragma unroll
        for (int k = 0; k < 5; k++) {
            xp[pr][k] = pack2(pts[0][pAc + k], pts[0][pBc + k]);
            yp[pr][k] = pack2(pts[1][pAc + k], pts[1][pBc + k]);
        }
    }
    const bool m1 = (tid + 384 < P1);
    #pragma unroll 1
    for (int cp = 0; cp < 8; cp++) {
        float wA[10], wB[10];
        #pragma unroll
        for (int q = 0; q < 10; q++) {
            wA[q] = w1s[(2 * cp) * 10 + q];
            wB[q] = w1s[(2 * cp + 1) * 10 + q];
        }
        float bbA = b1s[2 * cp], bbB = b1s[2 * cp + 1];
        u64 aA0 = pack2(bbA, bbA), aA1 = aA0;
        u64 aB0 = pack2(bbB, bbB), aB1 = aB0;
        #pragma unroll
        for (int k = 0; k < 5; k++) {
            u64 wa = pack2(wA[k], wA[k]);
            fma2(aA0, wa, xp[0][k]); fma2(aA1, wa, xp[1][k]);
            u64 wb = pack2(wB[k], wB[k]);
            fma2(aB0, wb, xp[0][k]); fma2(aB1, wb, xp[1][k]);
        }
        #pragma unroll
        for (int k = 0; k < 5; k++) {
            u64 wa = pack2(wA[5 + k], wA[5 + k]);
            fma2(aA0, wa, yp[0][k]); fma2(aA1, wa, yp[1][k]);
            u64 wb = pack2(wB[5 + k], wB[5 + k]);
            fma2(aB0, wb, yp[0][k]); fma2(aB1, wb, yp[1][k]);
        }
        float vA[4], vB[4];
        unpack2(aA0, vA[0], vA[1]); unpack2(aA1, vA[2], vA[3]);
        unpack2(aB0, vB[0], vB[1]); unpack2(aB1, vB[2], vB[3]);
        #pragma unroll
        for (int j = 0; j < 4; j++) {
            if (j == 3 && !m1) break;
            int p = tid + j * 128;
            float a = fmaxf(vA[j], 0.f), b = fmaxf(vB[j], 0.f);
            unsigned big = cvt2(a, b);
            float loF = __int_as_float(big << 16);
            float hiF = __int_as_float(big & 0xffff0000u);
            unsigned res = cvt2(a - loF, b - hiF);
            h1b32[p * 9 + cp] = big;
            h1r32[p * 9 + cp] = res;
        }
    }
    __syncthreads();

    // ---- conv2 via bf16 HMMA: C[16co x 8p] tiles, 5 shifts accumulated ----
    const int lane = tid & 31, wrp = tid >> 5;
    const int g = lane >> 2, tq = lane & 3;

    float acc[16][4];
    #pragma unroll
    for (int i = 0; i < 16; i++) {
        acc[i][0] = 0.f; acc[i][1] = 0.f; acc[i][2] = 0.f; acc[i][3] = 0.f;
    }

    const unsigned* w2b32 = reinterpret_cast<const unsigned*>(w2b);
    const unsigned* w2r32 = reinterpret_cast<const unsigned*>(w2r);

    #pragma unroll
    for (int s = 0; s < 5; s++) {
        const int awl = (g * 5 + s) * 8 + tq;
        const int awh = ((g + 8) * 5 + s) * 8 + tq;
        unsigned ab0 = w2b32[awl],     ab1 = w2b32[awh];
        unsigned ab2 = w2b32[awl + 4], ab3 = w2b32[awh + 4];
        unsigned ar0 = w2r32[awl],     ar1 = w2r32[awh];
        unsigned ar2 = w2r32[awl + 4], ar3 = w2r32[awh + 4];
        #pragma unroll
        for (int i = 0; i < 16; i++) {
            int nb = wrp + 4 * i;
            if (nb >= 63) break;
            int pw = (nb * 8 + g + s) * 9 + tq;
            unsigned bb0 = h1b32[pw], bb1 = h1b32[pw + 4];
            unsigned br0 = h1r32[pw], br1 = h1r32[pw + 4];
            mma_bf16(acc[i], ab0, ab1, ab2, ab3, bb0, bb1);
            mma_bf16(acc[i], ab0, ab1, ab2, ab3, br0, br1);
            mma_bf16(acc[i], ar0, ar1, ar2, ar3, bb0, bb1);
        }
    }

    // ---- epilogue: bias + relu per position, point-sum ----
    const float b2g = b2s[g], b2g8 = b2s[g + 8];
    float sg = 0.f, sg8 = 0.f;
    #pragma unroll
    for (int i = 0; i < 16; i++) {
        int nb = wrp + 4 * i;
        if (nb >= 63) break;
        sg  += fmaxf(acc[i][0] + b2g, 0.f)  + fmaxf(acc[i][1] + b2g, 0.f);
        sg8 += fmaxf(acc[i][2] + b2g8, 0.f) + fmaxf(acc[i][3] + b2g8, 0.f);
    }
    sg  += __shfl_xor_sync(0xffffffffu, sg, 1);
    sg  += __shfl_xor_sync(0xffffffffu, sg, 2);
    sg8 += __shfl_xor_sync(0xffffffffu, sg8, 1);
    sg8 += __shfl_xor_sync(0xffffffffu, sg8, 2);
    if (tq == 0) { redw[wrp][g] = sg; redw[wrp][g + 8] = sg8; }
    __syncthreads();
    if (tid < 16)
        d_elem[(size_t)(t * EE + e) * 16 + tid] =
            redw[0][tid] + redw[1][tid] + redw[2][tid] + redw[3][tid];
}

// ---------------- K2: s0 partials (+zero gmax)  grid (32, T), block 256 ----------------
__global__ __launch_bounds__(256) void k_s0p() {
    const int t = blockIdx.y, chunk = blockIdx.x, tid = threadIdx.x;
    const int d = tid & 15, grp = tid >> 4;   // 16 groups x 4 e's
    const int e0 = chunk * 64;
    float acc = 0.f;
    #pragma unroll
    for (int i = 0; i < 4; i++)
        acc += d_elem[(size_t)(t * EE + e0 + grp + 16 * i) * 16 + d];
    __shared__ float r[256];
    r[tid] = acc; __syncthreads();
    if (tid < 128) r[tid] += r[tid + 128];
    __syncthreads();
    if (tid < 64) r[tid] += r[tid + 64];
    __syncthreads();
    if (tid < 32) r[tid] += r[tid + 32];
    __syncthreads();
    if (tid < 16) d_s0p[(t * 32 + chunk) * 16 + tid] = r[tid] + r[tid + 16];
    if (chunk == 0 && tid < 128) d_gmax[t * 128 + tid] = 0;
}

// ---------------- K3: layer1 -> d_g1 + s1 partials  grid (128, T), block 256 ----------------
__global__ __launch_bounds__(256) void k_l1(
    const float* __restrict__ A1, const float* __restrict__ B1)
{
    __shared__ float C1s[16][128];
    __shared__ float elems[16][16];
    __shared__ float r[256];
    __shared__ float s0s[16];

    const int tid = threadIdx.x, t = blockIdx.y, chunk = blockIdx.x;
    const int e0 = chunk * 16;
    const int h = tid & 127, half = tid >> 7;

    if (tid < 256) {
        int i = tid;
        if (i < 256) elems[i >> 4][i & 15] = d_elem[(size_t)(t * EE + e0) * 16 + i];
    }
    for (int i = tid; i < 2048; i += 256)
        C1s[i >> 7][i & 127] = A1[t * 2048 + i] - B1[t * 2048 + i];
    if (tid < 16) {
        float s = 0.f;
        #pragma unroll
        for (int b = 0; b < 32; b++) s += d_s0p[(t * 32 + b) * 16 + tid];
        s0s[tid] = s;
    }
    __syncthreads();

    float c1r[16];
    #pragma unroll
    for (int d = 0; d < 16; d++) c1r[d] = C1s[d][h];
    float sbl1 = 0.f;
    #pragma unroll
    for (int d = 0; d < 16; d++)
        sbl1 = fmaf(s0s[d], B1[t * 2048 + d * 128 + h], sbl1);

    float accs = 0.f;
    const int eib = half * 8;
    #pragma unroll
    for (int ei = 0; ei < 8; ei++) {
        float v = sbl1;
        #pragma unroll
        for (int d = 0; d < 16; d++) v = fmaf(elems[eib + ei][d], c1r[d], v);
        v = fmaxf(v, 0.f);
        d_g1[(size_t)(t * EE + e0 + eib + ei) * 128 + h] = v;
        accs += v;
    }
    r[tid] = accs;
    __syncthreads();
    if (tid < 128)
        d_s1p[(t * 128 + chunk) * 128 + tid] = r[tid] + r[tid + 128];
}

// ---------------- K4: layer2 GEMM + max  grid (128, T), block 256 ----------------
__global__ __launch_bounds__(256) void k_l2(
    const float* __restrict__ A2, const float* __restrict__ B2)
{
    __shared__ __align__(8) float g1T[128][18];   // [feature d][ei 0..15]
    __shared__ float C2q[2][16][128];
    __shared__ float r[256];
    __shared__ float s1s[128];

    const int tid = threadIdx.x, t = blockIdx.y, chunk = blockIdx.x;
    const int e0 = chunk * 16;
    const int h = tid & 127, half = tid >> 7;
    const int tb = t * 16384;

    // prefetch first C2 slab early
    float pa_[8], pb_[8];
    #pragma unroll
    for (int k = 0; k < 8; k++) {
        int idx = tid + k * 256;
        pa_[k] = A2[tb + idx];
        pb_[k] = B2[tb + idx];
    }

    // s1 combine (128 partials, 64 per half)
    {
        float a = 0.f;
        #pragma unroll 4
        for (int s = 0; s < 64; s++)
            a += d_s1p[(t * 128 + half * 64 + s) * 128 + h];
        r[tid] = a;
    }

    // g1 tile load (transposed into smem)
    for (int i = tid; i < 2048; i += 256) {
        int ei = i >> 7, hh = i & 127;
        g1T[hh][ei] = d_g1[(size_t)(t * EE + e0 + ei) * 128 + hh];
    }
    __syncthreads();
    if (tid < 128) s1s[tid] = r[tid] + r[tid + 128];
    __syncthreads();

    u64 acc2[4];
    #pragma unroll
    for (int pr = 0; pr < 4; pr++) acc2[pr] = 0ull;
    float sbp = 0.f;

    #pragma unroll 1
    for (int q = 0; q < 8; q++) {
        const int buf = q & 1;
        #pragma unroll
        for (int k = 0; k < 8; k++) {
            int d = 2 * k + half;
            sbp = fmaf(s1s[q * 16 + d], pb_[k], sbp);
            C2q[buf][d][h] = pa_[k] - pb_[k];
        }
        __syncthreads();
        if (q < 7) {
            const int base = tb + (q + 1) * 16 * 128;
            #pragma unroll
            for (int k = 0; k < 8; k++) {
                int idx = tid + k * 256;
                pa_[k] = A2[base + idx];
                pb_[k] = B2[base + idx];
            }
        }
        #pragma unroll 4
        for (int dd = 0; dd < 16; dd++) {
            float c = C2q[buf][dd][h];
            u64 cp = pack2(c, c);
            const u64* grow = reinterpret_cast<const u64*>(&g1T[q * 16 + dd][half * 8]);
            #pragma unroll
            for (int pr = 0; pr < 4; pr++) fma2(acc2[pr], grow[pr], cp);
        }
        __syncthreads();
    }

    // combine sb halves (even/odd d parity)
    r[tid] = sbp;
    __syncthreads();
    const float sb = r[h] + r[h + 128];

    float m = 0.f;   // relu floor == max identity
    #pragma unroll
    for (int pr = 0; pr < 4; pr++) {
        float a, b;
        unpack2(acc2[pr], a, b);
        m = fmaxf(m, fmaxf(a + sb, b + sb));
    }
    atomicMax(&d_gmax[t * 128 + h], __float_as_int(m));
}

// ---------------- K5: gf + final matmul partials  grid 8, block 256 ----------------
__global__ __launch_bounds__(256) void k_gfw(const float* __restrict__ Aout,
                                             const float* __restrict__ Wm)
{
    __shared__ float gv[512];
    __shared__ float gfs[64];
    __shared__ float r[256];
    const int tid = threadIdx.x, blk = blockIdx.x;

    for (int i = tid; i < 512; i += 256) gv[i] = __int_as_float(d_gmax[i]);
    __syncthreads();

    const int j = tid >> 2, sub = tid & 3;
    const int gi = blk * 64 + j;          // global gf index = t*128 + o
    const int t2 = gi >> 7, o = gi & 127;
    float a = 0.f;
    #pragma unroll 4
    for (int k = 0; k < 32; k++)
        a = fmaf(gv[t2 * 128 + sub * 32 + k],
                 Aout[t2 * 16384 + (sub * 32 + k) * 128 + o], a);
    r[tid] = a;
    __syncthreads();
    if (sub == 0) gfs[j] = r[tid] + r[tid + 1] + r[tid + 2] + r[tid + 3];
    __syncthreads();

    float acc = 0.f;
    const int i0 = blk * 64;
    #pragma unroll 8
    for (int i = 0; i < 64; i++)
        acc = fmaf(gfs[i], Wm[(i0 + i) * 256 + tid], acc);
    d_fpart[blk * 256 + tid] = acc;
}

// ---------------- K6: combine  grid 1, block 256 ----------------
__global__ void k_fin2(const float* __restrict__ bm, float* __restrict__ out) {
    const int tid = threadIdx.x;
    float a = bm[tid];
    #pragma unroll
    for (int b = 0; b < 8; b++) a += d_fpart[b * 256 + tid];
    out[tid] = a;
}

// ---------------- launch ----------------
extern "C" void kernel_launch(void* const* d_in, const int* in_sizes, int n_in,
                              void* d_out, int out_size)
{
    const float* points = (const float*)d_in[0];
    const float* w1     = (const float*)d_in[1];
    const float* b1     = (const float*)d_in[2];
    const float* w2     = (const float*)d_in[3];
    const float* b2     = (const float*)d_in[4];
    const float* A1     = (const float*)d_in[5];
    const float* B1     = (const float*)d_in[6];
    const float* A2     = (const float*)d_in[7];
    const float* B2     = (const float*)d_in[8];
    const float* Aout   = (const float*)d_in[9];
    const float* Wm     = (const float*)d_in[10];
    const float* bm     = (const float*)d_in[11];
    float* out = (float*)d_out;

    k_conv<<<dim3(EE, TT), 128>>>(points, w1, b1, w2, b2);
    k_s0p<<<dim3(32, TT), 256>>>();
    k_l1<<<dim3(128, TT), 256>>>(A1, B1);
    k_l2<<<dim3(128, TT), 256>>>(A2, B2);
    k_gfw<<<8, 256>>>(Aout, Wm);
    k_fin2<<<1, 256>>>(bm, out);
}